// round 8
// baseline (speedup 1.0000x reference)
#include <cuda_runtime.h>
#include <cuda_bf16.h>
#include <cstdint>
#include <float.h>

#define BATCHN 256
#define DDIM   512
#define HDIM   2048
#define SLOTSN 32768
#define CCAP   512
#define CDELTA 12.0f
#define PART_ELEMS (32*256*512)
#define K6_MK   (6*DDIM)      // 3072 (3-way split, 6 terms: base GEMM only)

// ---------------- scratch (static device globals; no allocation) ----------------
__device__ float g_K[BATCHN*DDIM];
__device__ float g_V[BATCHN*DDIM];
__device__ float g_G[BATCHN*BATCHN];
__device__ float g_base[(size_t)BATCHN*SLOTSN];   // 32 MB raw scores
__device__ float g_E[(size_t)BATCHN*SLOTSN];      // 32 MB exp(scores - m)  (fp32, round-2 style)
__device__ float g_m[BATCHN];
__device__ float g_Z0[BATCHN];
__device__ float g_Zc[BATCHN];
__device__ float g_R0[BATCHN*DDIM];
__device__ float g_Rc[BATCHN*DDIM];
__device__ float g_cand_val[BATCHN*CCAP];
__device__ int   g_cand_slot[BATCHN*CCAP];
__device__ int   g_cand_cnt[BATCHN];
__device__ int   g_slots[BATCHN];
__device__ int   g_nxt[BATCHN];
__device__ float g_Ccat[BATCHN*2*BATCHN];
__device__ float g_Vcat[2*BATCHN*DDIM];
__device__ float g_Merged[BATCHN*2*DDIM];
__device__ float g_Hidden[BATCHN*HDIM];
__device__ float g_Part[PART_ELEMS];

// 6-term split-bf16 operands for the base GEMM only
__device__ unsigned short g_MKp6[(size_t)SLOTSN*K6_MK];  // 201 MB
__device__ unsigned short g_KpA6[BATCHN*K6_MK];

// ---------------- helpers ----------------
__device__ __forceinline__ unsigned short f2bf(float x) {
    __nv_bfloat16 h = __float2bfloat16(x);
    return *reinterpret_cast<unsigned short*>(&h);
}
__device__ __forceinline__ float bf2f(unsigned short u) {
    __nv_bfloat16 h = *reinterpret_cast<__nv_bfloat16*>(&u);
    return __bfloat162float(h);
}
__device__ __forceinline__ void cp16(unsigned d, const void* s) {
    asm volatile("cp.async.cg.shared.global [%0], [%1], 16;\n" :: "r"(d), "l"(s));
}
#define CP_COMMIT() asm volatile("cp.async.commit_group;\n")
#define MMA16816(C0,C1,C2,C3,A0,A1,A2,A3,B0,B1) \
  asm volatile("mma.sync.aligned.m16n8k16.row.col.f32.bf16.bf16.f32 " \
    "{%0,%1,%2,%3},{%4,%5,%6,%7},{%8,%9},{%0,%1,%2,%3};\n" \
    : "+f"(C0),"+f"(C1),"+f"(C2),"+f"(C3) \
    : "r"(A0),"r"(A1),"r"(A2),"r"(A3),"r"(B0),"r"(B1))

// 3-way split, 6 terms (fp32-class): A=[a1|a1|a2|a1|a2|a3], B=[b1|b2|b1|b3|b2|b1]
// products: a1b1 + a1b2 + a2b1 + a1b3 + a2b2 + a3b1
__global__ void pack_split6_kernel(const float* __restrict__ X, unsigned short* __restrict__ Y,
                                   int total, int Kd, int bmode)
{
    int idx = blockIdx.x * 256 + threadIdx.x;
    if (idx >= total) return;
    int r = idx / Kd, k = idx - r * Kd;
    float x = X[idx];
    unsigned short u1 = f2bf(x);            float f1 = bf2f(u1);
    unsigned short u2 = f2bf(x - f1);       float f2_ = bf2f(u2);
    unsigned short u3 = f2bf(x - f1 - f2_);
    size_t ro = (size_t)r * (6 * Kd);
    if (!bmode) {
        Y[ro + k] = u1; Y[ro + Kd + k] = u1; Y[ro + 2*Kd + k] = u2;
        Y[ro + 3*Kd + k] = u1; Y[ro + 4*Kd + k] = u2; Y[ro + 5*Kd + k] = u3;
    } else {
        Y[ro + k] = u1; Y[ro + Kd + k] = u2; Y[ro + 2*Kd + k] = u1;
        Y[ro + 3*Kd + k] = u3; Y[ro + 4*Kd + k] = u2; Y[ro + 5*Kd + k] = u1;
    }
}

// ---------------- bf16 TN tensor-core GEMM (base only this round) ----------------
__global__ __launch_bounds__(256, 2) void mma_tn_kernel(
    const unsigned short* __restrict__ A, const unsigned short* __restrict__ B,
    float* __restrict__ C, const float* __restrict__ bias,
    int M, int N, int Kd, int kChunk, int relu)
{
    __shared__ unsigned short As[2][128*40];
    __shared__ unsigned short Bs[2][128*40];
    const int tid = threadIdx.x;
    const int wid = tid >> 5, lane = tid & 31;
    const int wm = wid >> 2, wn = wid & 3;
    const int g = lane >> 2, t = lane & 3;
    const int m0 = blockIdx.y * 128, n0 = blockIdx.x * 128;
    const int k0 = blockIdx.z * kChunk;
    const int nIter = kChunk >> 5;

    const int lr = tid >> 2;
    const int lc = (tid & 3) << 3;
    const unsigned short* Ag = A + (size_t)(m0 + lr) * Kd + k0 + lc;
    const unsigned short* Bg = B + (size_t)(n0 + lr) * Kd + k0 + lc;
    const size_t rowStep = (size_t)64 * Kd;

    unsigned dstA[2], dstB[2];
    dstA[0] = (unsigned)__cvta_generic_to_shared(&As[0][lr*40 + lc]);
    dstA[1] = (unsigned)__cvta_generic_to_shared(&As[1][lr*40 + lc]);
    dstB[0] = (unsigned)__cvta_generic_to_shared(&Bs[0][lr*40 + lc]);
    dstB[1] = (unsigned)__cvta_generic_to_shared(&Bs[1][lr*40 + lc]);

    float acc[4][4][4];
    #pragma unroll
    for (int mi = 0; mi < 4; mi++)
        #pragma unroll
        for (int ni = 0; ni < 4; ni++)
            #pragma unroll
            for (int q = 0; q < 4; q++) acc[mi][ni][q] = 0.f;

    {
        cp16(dstA[0], Ag); cp16(dstA[0] + 5120, Ag + rowStep);
        cp16(dstB[0], Bg); cp16(dstB[0] + 5120, Bg + rowStep);
        CP_COMMIT();
    }

    for (int kk = 0; kk < nIter; kk++) {
        int cur = kk & 1;
        if (kk + 1 < nIter) {
            const unsigned short* ap = Ag + ((kk+1) << 5);
            const unsigned short* bp = Bg + ((kk+1) << 5);
            cp16(dstA[cur^1], ap); cp16(dstA[cur^1] + 5120, ap + rowStep);
            cp16(dstB[cur^1], bp); cp16(dstB[cur^1] + 5120, bp + rowStep);
            CP_COMMIT();
            asm volatile("cp.async.wait_group 1;\n");
        } else {
            asm volatile("cp.async.wait_group 0;\n");
        }
        __syncthreads();

        const unsigned short* as_ = As[cur];
        const unsigned short* bs_ = Bs[cur];
        #pragma unroll
        for (int ks = 0; ks < 2; ks++) {
            unsigned a[4][4], b[4][2];
            #pragma unroll
            for (int mi = 0; mi < 4; mi++) {
                int row = wm*64 + mi*16;
                const unsigned short* p  = &as_[(row + g)*40 + ks*16 + 2*t];
                const unsigned short* p2 = p + 8*40;
                a[mi][0] = *(const unsigned*)p;
                a[mi][1] = *(const unsigned*)p2;
                a[mi][2] = *(const unsigned*)(p + 8);
                a[mi][3] = *(const unsigned*)(p2 + 8);
            }
            #pragma unroll
            for (int ni = 0; ni < 4; ni++) {
                int col = wn*32 + ni*8;
                const unsigned short* p = &bs_[(col + g)*40 + ks*16 + 2*t];
                b[ni][0] = *(const unsigned*)p;
                b[ni][1] = *(const unsigned*)(p + 8);
            }
            #pragma unroll
            for (int mi = 0; mi < 4; mi++)
                #pragma unroll
                for (int ni = 0; ni < 4; ni++)
                    MMA16816(acc[mi][ni][0], acc[mi][ni][1], acc[mi][ni][2], acc[mi][ni][3],
                             a[mi][0], a[mi][1], a[mi][2], a[mi][3], b[ni][0], b[ni][1]);
        }
        __syncthreads();
    }

    const bool direct = (gridDim.z == 1);
    float* Cz = direct ? C : C + (size_t)blockIdx.z * M * N;
    #pragma unroll
    for (int mi = 0; mi < 4; mi++)
        #pragma unroll
        for (int ni = 0; ni < 4; ni++) {
            int row = m0 + wm*64 + mi*16 + g;
            int col = n0 + wn*32 + ni*8 + 2*t;
            float v0 = acc[mi][ni][0], v1 = acc[mi][ni][1];
            float v2 = acc[mi][ni][2], v3 = acc[mi][ni][3];
            if (direct) {
                if (bias) { float b0 = bias[col], b1 = bias[col+1]; v0 += b0; v1 += b1; v2 += b0; v3 += b1; }
                if (relu) { v0 = fmaxf(v0,0.f); v1 = fmaxf(v1,0.f); v2 = fmaxf(v2,0.f); v3 = fmaxf(v3,0.f); }
            }
            *(float2*)&Cz[(size_t)row * N + col]       = make_float2(v0, v1);
            *(float2*)&Cz[(size_t)(row + 8) * N + col] = make_float2(v2, v3);
        }
}

// ---------------- fp32 SIMT GEMM (round-2, known-good) ----------------
template<bool BT>
__global__ __launch_bounds__(256, 2) void gemm_kernel(
    const float* __restrict__ A, const float* __restrict__ B, float* __restrict__ C,
    int M, int N, int Kd, int kChunk)
{
    __shared__ float As[8][128];
    __shared__ float Bs[8][128];
    const int tid = threadIdx.x;
    const int tx = tid & 15, ty = tid >> 4;
    const int bn = blockIdx.x, bm = blockIdx.y, bz = blockIdx.z;
    const int k0 = bz * kChunk;

    const int ar = tid >> 1, aq = (tid & 1) << 2;
    const float* Arow = A + (size_t)(bm*128 + ar)*Kd + aq;
    const float* Brow;
    if (BT) Brow = B + (size_t)(bn*128 + ar)*Kd + aq;
    else    Brow = B + (size_t)(k0 + (tid >> 5))*N + bn*128 + ((tid & 31) << 2);

    float acc[8][8];
    #pragma unroll
    for (int r = 0; r < 8; r++)
        #pragma unroll
        for (int c = 0; c < 8; c++) acc[r][c] = 0.f;

    for (int k = k0; k < k0 + kChunk; k += 8) {
        float4 av = *(const float4*)(Arow + k);
        As[aq+0][ar] = av.x; As[aq+1][ar] = av.y; As[aq+2][ar] = av.z; As[aq+3][ar] = av.w;
        if (BT) {
            float4 bv = *(const float4*)(Brow + k);
            Bs[aq+0][ar] = bv.x; Bs[aq+1][ar] = bv.y; Bs[aq+2][ar] = bv.z; Bs[aq+3][ar] = bv.w;
        } else {
            float4 bv = *(const float4*)Brow;
            *(float4*)&Bs[tid >> 5][(tid & 31) << 2] = bv;
            Brow += 8 * (size_t)N;
        }
        __syncthreads();
        #pragma unroll
        for (int kk = 0; kk < 8; kk++) {
            float a[8], b[8];
            *(float4*)&a[0] = *(const float4*)&As[kk][ty << 2];
            *(float4*)&a[4] = *(const float4*)&As[kk][64 + (ty << 2)];
            *(float4*)&b[0] = *(const float4*)&Bs[kk][tx << 2];
            *(float4*)&b[4] = *(const float4*)&Bs[kk][64 + (tx << 2)];
            #pragma unroll
            for (int r = 0; r < 8; r++)
                #pragma unroll
                for (int c = 0; c < 8; c++) acc[r][c] += a[r] * b[c];
        }
        __syncthreads();
    }

    float* Cout = C + (size_t)bz * M * N;
    const int mbase = bm*128, nbase = bn*128;
    #pragma unroll
    for (int rh = 0; rh < 2; rh++)
        #pragma unroll
        for (int rr = 0; rr < 4; rr++) {
            int r = rh*4 + rr;
            int m = mbase + rh*64 + (ty << 2) + rr;
            float* crow = Cout + (size_t)m * N + nbase;
            *(float4*)(crow + (tx << 2))      = make_float4(acc[r][0], acc[r][1], acc[r][2], acc[r][3]);
            *(float4*)(crow + 64 + (tx << 2)) = make_float4(acc[r][4], acc[r][5], acc[r][6], acc[r][7]);
        }
}

__global__ void reduce_kernel(const float* __restrict__ P, float* __restrict__ C,
                              const float* __restrict__ bias, int MN, int N, int split, int relu)
{
    int idx = blockIdx.x * 256 + threadIdx.x;
    if (idx >= MN) return;
    float s = 0.f;
    for (int z = 0; z < split; z++) s += P[(size_t)z * MN + idx];
    if (bias) s += bias[idx % N];
    if (relu) s = fmaxf(s, 0.f);
    C[idx] = s;
}

__global__ void rowmax_kernel(const float* __restrict__ base, float* __restrict__ m)
{
    int i = blockIdx.x, tid = threadIdx.x;
    const float* row = base + (size_t)i * SLOTSN;
    float mx = -FLT_MAX;
    for (int s = tid; s < SLOTSN; s += 256) mx = fmaxf(mx, row[s]);
    for (int o = 16; o; o >>= 1) mx = fmaxf(mx, __shfl_down_sync(0xffffffffu, mx, o));
    __shared__ float sh[8];
    if ((tid & 31) == 0) sh[tid >> 5] = mx;
    __syncthreads();
    if (tid == 0) { float r = sh[0]; for (int w = 1; w < 8; w++) r = fmaxf(r, sh[w]); m[i] = r; }
}

// E = exp(base - m) fp32 (round-2), Z0 row sums, candidate collection
__global__ void e_kernel(const float* __restrict__ base, const float* __restrict__ m,
                         float* __restrict__ E, float* __restrict__ Z0,
                         float* __restrict__ cval, int* __restrict__ cslot, int* __restrict__ ccnt)
{
    int i = blockIdx.x, tid = threadIdx.x;
    __shared__ int cnt;
    if (tid == 0) cnt = 0;
    __syncthreads();
    float mi = m[i], thr = mi - CDELTA, z = 0.f;
    const float* row = base + (size_t)i * SLOTSN;
    float* erow = E + (size_t)i * SLOTSN;
    for (int s = tid; s < SLOTSN; s += 256) {
        float b = row[s];
        float e = __expf(b - mi);
        erow[s] = e;
        z += e;
        if (b >= thr) {
            int idx = atomicAdd(&cnt, 1);
            if (idx < CCAP) { cval[i*CCAP + idx] = b; cslot[i*CCAP + idx] = s; }
        }
    }
    for (int o = 16; o; o >>= 1) z += __shfl_down_sync(0xffffffffu, z, o);
    __shared__ float sh[8];
    if ((tid & 31) == 0) sh[tid >> 5] = z;
    __syncthreads();
    if (tid == 0) { float r = 0; for (int w = 0; w < 8; w++) r += sh[w]; Z0[i] = r; ccnt[i] = cnt; }
}

__device__ __forceinline__ unsigned long long mk_key(float v, int slot)
{
    unsigned u = __float_as_uint(v);
    u = (u & 0x80000000u) ? ~u : (u | 0x80000000u);
    return ((unsigned long long)u << 32) | (unsigned)(0xFFFFFFFFu - (unsigned)slot);
}

// sequential slot chain — single warp, register-prefetched
__global__ void seq_kernel(const float* __restrict__ G,
                           const float* __restrict__ cval, const int* __restrict__ cslot,
                           const int* __restrict__ ccnt, const float* __restrict__ base,
                           int* __restrict__ slots_out, int* __restrict__ nxt_out)
{
    extern __shared__ short mapw[];
    __shared__ int slots_s[256];
    __shared__ unsigned char alive[256];
    __shared__ short nxt[256];
    int lane = threadIdx.x;

    for (int s = lane * 8; s < SLOTSN; s += 256)
        *(int4*)&mapw[s] = make_int4(-1, -1, -1, -1);
    for (int j = lane; j < 256; j += 32) { alive[j] = 0; nxt[j] = 1000; }
    __syncwarp();

    float4 rg0 = *(const float4*)&G[lane * 8];
    float4 rg1 = *(const float4*)&G[lane * 8 + 4];
    int pcnt = ccnt[0];
    float pv[4]; int ps[4];
    #pragma unroll
    for (int q = 0; q < 4; q++) {
        pv[q] = cval[lane + 32*q];
        ps[q] = cslot[lane + 32*q];
    }

    for (int i = 0; i < 256; i++) {
        float gv[8] = {rg0.x, rg0.y, rg0.z, rg0.w, rg1.x, rg1.y, rg1.z, rg1.w};
        int cnt = pcnt;
        float cv[4]; int cs[4];
        #pragma unroll
        for (int q = 0; q < 4; q++) { cv[q] = pv[q]; cs[q] = ps[q]; }

        if (i + 1 < 256) {
            rg0 = *(const float4*)&G[(i+1)*256 + lane*8];
            rg1 = *(const float4*)&G[(i+1)*256 + lane*8 + 4];
            pcnt = ccnt[i+1];
            #pragma unroll
            for (int q = 0; q < 4; q++) {
                pv[q] = cval[(i+1)*CCAP + lane + 32*q];
                ps[q] = cslot[(i+1)*CCAP + lane + 32*q];
            }
        }

        unsigned long long best = 0ull;
        #pragma unroll
        for (int q = 0; q < 8; q++) {
            int j = lane*8 + q;
            if (j < i && alive[j]) {
                unsigned long long k = mk_key(gv[q], slots_s[j]);
                if (k > best) best = k;
            }
        }
        bool needfull = (cnt > CCAP);
        bool found = false;
        if (!needfull) {
            #pragma unroll
            for (int q = 0; q < 4; q++) {
                int c = lane + 32*q;
                if (c < cnt && mapw[cs[q]] < 0) {
                    found = true;
                    unsigned long long k = mk_key(cv[q], cs[q]);
                    if (k > best) best = k;
                }
            }
            for (int c = lane + 128; c < cnt; c += 32) {
                int s = cslot[i*CCAP + c];
                if (mapw[s] < 0) {
                    found = true;
                    unsigned long long k = mk_key(cval[i*CCAP + c], s);
                    if (k > best) best = k;
                }
            }
        }
        if (!__any_sync(0xffffffffu, found) || needfull) {
            const float* row = base + (size_t)i * SLOTSN;
            for (int s4 = lane*4; s4 < SLOTSN; s4 += 128) {
                float4 v = *(const float4*)&row[s4];
                float vv[4] = {v.x, v.y, v.z, v.w};
                #pragma unroll
                for (int q = 0; q < 4; q++)
                    if (mapw[s4+q] < 0) {
                        unsigned long long k = mk_key(vv[q], s4+q);
                        if (k > best) best = k;
                    }
            }
        }
        #pragma unroll
        for (int o = 16; o; o >>= 1) {
            unsigned long long k = __shfl_xor_sync(0xffffffffu, best, o);
            if (k > best) best = k;
        }
        int slot = (int)(0xFFFFFFFFu - (unsigned)(best & 0xFFFFFFFFull));
        if (lane == 0) {
            int old = mapw[slot];
            if (old >= 0) { alive[old] = 0; nxt[old] = (short)i; }
            mapw[slot] = (short)i;
            alive[i] = 1;
            slots_s[i] = slot;
        }
        __syncwarp();
    }
    for (int j = lane; j < 256; j += 32) { slots_out[j] = slots_s[j]; nxt_out[j] = nxt[j]; }
}

// correction coefficients (round-2: reads fp32 E)
__global__ void cbuild_kernel(const float* __restrict__ G, const float* __restrict__ m,
                              const float* __restrict__ E, const int* __restrict__ slots,
                              const int* __restrict__ nxt, float* __restrict__ Ccat,
                              float* __restrict__ Zc)
{
    int i = blockIdx.x, j = threadIdx.x;
    float c1 = 0.f, c2 = 0.f;
    if (j < i && nxt[j] >= i) {
        c1 = __expf(G[i*256 + j] - m[i]);
        c2 = E[(size_t)i * SLOTSN + slots[j]];
    }
    Ccat[i*512 + j] = c1;
    Ccat[i*512 + 256 + j] = -c2;
    float d = c1 - c2;
    for (int o = 16; o; o >>= 1) d += __shfl_down_sync(0xffffffffu, d, o);
    __shared__ float sh[8];
    if ((j & 31) == 0) sh[j >> 5] = d;
    __syncthreads();
    if (j == 0) { float r = 0; for (int w = 0; w < 8; w++) r += sh[w]; Zc[i] = r; }
}

__global__ void vcat_kernel(const float* __restrict__ V, const float* __restrict__ mv,
                            const int* __restrict__ slots, float* __restrict__ Vcat)
{
    int j = blockIdx.x, d = threadIdx.x;
    if (j < 256) Vcat[(size_t)j*512 + d] = V[j*512 + d];
    else         Vcat[(size_t)j*512 + d] = mv[(size_t)slots[j-256]*512 + d];
}

__global__ void merged_kernel(const float* __restrict__ S, const float* __restrict__ R0,
                              const float* __restrict__ Rc, const float* __restrict__ Z0,
                              const float* __restrict__ Zc, float* __restrict__ Mg)
{
    int i = blockIdx.x, d = threadIdx.x;
    Mg[i*1024 + d] = S[i*512 + d];
    Mg[i*1024 + 512 + d] = (R0[i*512 + d] + Rc[i*512 + d]) / (Z0[i] + Zc[i]);
}

extern "C" void kernel_launch(void* const* d_in, const int* in_sizes, int n_in,
                              void* d_out, int out_size)
{
    (void)in_sizes; (void)n_in; (void)out_size;
    const float* S  = (const float*)d_in[0];
    const float* MK = (const float*)d_in[1];
    const float* MV = (const float*)d_in[2];
    const float* Wk = (const float*)d_in[3];
    const float* bk = (const float*)d_in[4];
    const float* Wv = (const float*)d_in[5];
    const float* bv = (const float*)d_in[6];
    const float* W1 = (const float*)d_in[7];
    const float* b1 = (const float*)d_in[8];
    const float* W2 = (const float*)d_in[9];
    const float* b2 = (const float*)d_in[10];
    float* out = (float*)d_out;

    float *pK, *pV, *pG, *pBase, *pE, *pm, *pZ0, *pZc, *pR0, *pRc;
    float *pCval, *pCcat, *pVcat, *pMg, *pHid, *pPart;
    int *pCslot, *pCcnt, *pSlots, *pNxt;
    unsigned short *pMKp6, *pKpA6;
    cudaGetSymbolAddress((void**)&pK, g_K);
    cudaGetSymbolAddress((void**)&pV, g_V);
    cudaGetSymbolAddress((void**)&pG, g_G);
    cudaGetSymbolAddress((void**)&pBase, g_base);
    cudaGetSymbolAddress((void**)&pE, g_E);
    cudaGetSymbolAddress((void**)&pm, g_m);
    cudaGetSymbolAddress((void**)&pZ0, g_Z0);
    cudaGetSymbolAddress((void**)&pZc, g_Zc);
    cudaGetSymbolAddress((void**)&pR0, g_R0);
    cudaGetSymbolAddress((void**)&pRc, g_Rc);
    cudaGetSymbolAddress((void**)&pCval, g_cand_val);
    cudaGetSymbolAddress((void**)&pCslot, g_cand_slot);
    cudaGetSymbolAddress((void**)&pCcnt, g_cand_cnt);
    cudaGetSymbolAddress((void**)&pSlots, g_slots);
    cudaGetSymbolAddress((void**)&pNxt, g_nxt);
    cudaGetSymbolAddress((void**)&pCcat, g_Ccat);
    cudaGetSymbolAddress((void**)&pVcat, g_Vcat);
    cudaGetSymbolAddress((void**)&pMg, g_Merged);
    cudaGetSymbolAddress((void**)&pHid, g_Hidden);
    cudaGetSymbolAddress((void**)&pPart, g_Part);
    cudaGetSymbolAddress((void**)&pMKp6, g_MKp6);
    cudaGetSymbolAddress((void**)&pKpA6, g_KpA6);

    dim3 thr(256);

    // pack mem_keys for the base GEMM (6-term B-mode)
    pack_split6_kernel<<<(SLOTSN*DDIM + 255)/256, thr>>>(MK, pMKp6, SLOTSN*DDIM, DDIM, 1);

    // projections (fp32 SIMT, exact): K = S@Wk^T, V = S@Wv^T   (biases are zero but kept)
    gemm_kernel<true><<<dim3(4, 2, 8), thr>>>(S, Wk, pPart, 256, 512, 512, 64);
    reduce_kernel<<<512, 256>>>(pPart, pK, bk, 256*512, 512, 8, 0);
    gemm_kernel<true><<<dim3(4, 2, 8), thr>>>(S, Wv, pPart, 256, 512, 512, 64);
    reduce_kernel<<<512, 256>>>(pPart, pV, bv, 256*512, 512, 8, 0);

    pack_split6_kernel<<<(BATCHN*DDIM + 255)/256, thr>>>(pK, pKpA6, BATCHN*DDIM, DDIM, 0);

    // Gram G = K@K^T (fp32 SIMT — exact for argmax)
    gemm_kernel<true><<<dim3(2, 2, 16), thr>>>(pK, pK, pPart, 256, 256, 512, 32);
    reduce_kernel<<<256, 256>>>(pPart, pG, nullptr, 256*256, 256, 16, 0);

    // base = K @ mem_keys^T (tensor cores, 6-term split-bf16 = fp32-class)
    mma_tn_kernel<<<dim3(256, 2, 1), thr>>>(pKpA6, pMKp6, pBase, nullptr, 256, 32768, K6_MK, K6_MK, 0);
    rowmax_kernel<<<256, 256>>>(pBase, pm);
    e_kernel<<<256, 256>>>(pBase, pm, pE, pZ0, pCval, pCslot, pCcnt);

    // R0 = E @ mem_vals (fp32 SIMT, round-2, split-K 32)
    gemm_kernel<false><<<dim3(4, 2, 32), thr>>>(pE, MV, pPart, 256, 512, 32768, 1024);
    reduce_kernel<<<512, 256>>>(pPart, pR0, nullptr, 256*512, 512, 32, 0);

    // sequential slot chain (1 warp)
    cudaFuncSetAttribute(seq_kernel, cudaFuncAttributeMaxDynamicSharedMemorySize, SLOTSN * 2);
    seq_kernel<<<1, 32, SLOTSN * 2>>>(pG, pCval, pCslot, pCcnt, pBase, pSlots, pNxt);

    // per-step corrections: Rc = Ccat @ Vcat (fp32 SIMT)
    cbuild_kernel<<<256, 256>>>(pG, pm, pE, pSlots, pNxt, pCcat, pZc);
    vcat_kernel<<<512, 512>>>(pV, MV, pSlots, pVcat);
    gemm_kernel<false><<<dim3(4, 2, 8), thr>>>(pCcat, pVcat, pPart, 256, 512, 512, 64);
    reduce_kernel<<<512, 256>>>(pPart, pRc, nullptr, 256*512, 512, 8, 0);

    merged_kernel<<<256, 512>>>(S, pR0, pRc, pZ0, pZc, pMg);

    // MLP (fp32 SIMT, round-2)
    gemm_kernel<true><<<dim3(16, 2, 8), thr>>>(pMg, W1, pPart, 256, 2048, 1024, 128);
    reduce_kernel<<<2048, 256>>>(pPart, pHid, b1, 256*2048, 2048, 8, 1);
    gemm_kernel<true><<<dim3(4, 2, 32), thr>>>(pHid, W2, pPart, 256, 512, 2048, 64);
    reduce_kernel<<<512, 256>>>(pPart, out, b2, 256*512, 512, 32, 0);
}

// round 9
// speedup vs baseline: 1.5421x; 1.5421x over previous
#include <cuda_runtime.h>
#include <cuda_bf16.h>
#include <cstdint>
#include <float.h>

#define BATCHN 256
#define DDIM   512
#define HDIM   2048
#define SLOTSN 32768
#define CCAP   512
#define CDELTA 12.0f
#define PART_ELEMS (32*256*512)
#define K6_MK   (6*DDIM)      // 3072 (3-way split, 6 terms: base GEMM only)

// ---------------- scratch (static device globals; no allocation) ----------------
__device__ float g_K[BATCHN*DDIM];
__device__ float g_V[BATCHN*DDIM];
__device__ float g_G[BATCHN*BATCHN];
__device__ float g_base[(size_t)BATCHN*SLOTSN];   // 32 MB raw scores
__device__ float g_E[(size_t)BATCHN*SLOTSN];      // 32 MB exp(scores - m)  (fp32, round-2 style)
__device__ float g_m[BATCHN];
__device__ float g_Z0[BATCHN];
__device__ float g_Zc[BATCHN];
__device__ float g_R0[BATCHN*DDIM];
__device__ float g_Rc[BATCHN*DDIM];
__device__ float g_cand_val[BATCHN*CCAP];
__device__ int   g_cand_slot[BATCHN*CCAP];
__device__ int   g_cand_cnt[BATCHN];
__device__ int   g_slots[BATCHN];
__device__ int   g_nxt[BATCHN];
__device__ float g_Ccat[BATCHN*2*BATCHN];
__device__ float g_Vcat[2*BATCHN*DDIM];
__device__ float g_Merged[BATCHN*2*DDIM];
__device__ float g_Hidden[BATCHN*HDIM];
__device__ float g_Part[PART_ELEMS];

// 6-term split-bf16 operands for the base GEMM only
__device__ unsigned short g_MKp6[(size_t)SLOTSN*K6_MK];  // 201 MB
__device__ unsigned short g_KpA6[BATCHN*K6_MK];

// ---------------- helpers ----------------
__device__ __forceinline__ unsigned short f2bf(float x) {
    __nv_bfloat16 h = __float2bfloat16(x);
    return *reinterpret_cast<unsigned short*>(&h);
}
__device__ __forceinline__ float bf2f(unsigned short u) {
    __nv_bfloat16 h = *reinterpret_cast<__nv_bfloat16*>(&u);
    return __bfloat162float(h);
}
__device__ __forceinline__ void cp16(unsigned d, const void* s) {
    asm volatile("cp.async.cg.shared.global [%0], [%1], 16;\n" :: "r"(d), "l"(s));
}
#define CP_COMMIT() asm volatile("cp.async.commit_group;\n")
#define MMA16816(C0,C1,C2,C3,A0,A1,A2,A3,B0,B1) \
  asm volatile("mma.sync.aligned.m16n8k16.row.col.f32.bf16.bf16.f32 " \
    "{%0,%1,%2,%3},{%4,%5,%6,%7},{%8,%9},{%0,%1,%2,%3};\n" \
    : "+f"(C0),"+f"(C1),"+f"(C2),"+f"(C3) \
    : "r"(A0),"r"(A1),"r"(A2),"r"(A3),"r"(B0),"r"(B1))

// 3-way split, 6 terms (fp32-class): A=[a1|a1|a2|a1|a2|a3], B=[b1|b2|b1|b3|b2|b1]
// products: a1b1 + a1b2 + a2b1 + a1b3 + a2b2 + a3b1
__global__ void pack_split6_kernel(const float* __restrict__ X, unsigned short* __restrict__ Y,
                                   int total, int Kd, int bmode)
{
    int idx = blockIdx.x * 256 + threadIdx.x;
    if (idx >= total) return;
    int r = idx / Kd, k = idx - r * Kd;
    float x = X[idx];
    unsigned short u1 = f2bf(x);            float f1 = bf2f(u1);
    unsigned short u2 = f2bf(x - f1);       float f2_ = bf2f(u2);
    unsigned short u3 = f2bf(x - f1 - f2_);
    size_t ro = (size_t)r * (6 * Kd);
    if (!bmode) {
        Y[ro + k] = u1; Y[ro + Kd + k] = u1; Y[ro + 2*Kd + k] = u2;
        Y[ro + 3*Kd + k] = u1; Y[ro + 4*Kd + k] = u2; Y[ro + 5*Kd + k] = u3;
    } else {
        Y[ro + k] = u1; Y[ro + Kd + k] = u2; Y[ro + 2*Kd + k] = u1;
        Y[ro + 3*Kd + k] = u3; Y[ro + 4*Kd + k] = u2; Y[ro + 5*Kd + k] = u1;
    }
}

// ---------------- bf16 TN tensor-core GEMM (base only this round) ----------------
__global__ __launch_bounds__(256, 2) void mma_tn_kernel(
    const unsigned short* __restrict__ A, const unsigned short* __restrict__ B,
    float* __restrict__ C, const float* __restrict__ bias,
    int M, int N, int Kd, int kChunk, int relu)
{
    __shared__ unsigned short As[2][128*40];
    __shared__ unsigned short Bs[2][128*40];
    const int tid = threadIdx.x;
    const int wid = tid >> 5, lane = tid & 31;
    const int wm = wid >> 2, wn = wid & 3;
    const int g = lane >> 2, t = lane & 3;
    const int m0 = blockIdx.y * 128, n0 = blockIdx.x * 128;
    const int k0 = blockIdx.z * kChunk;
    const int nIter = kChunk >> 5;

    const int lr = tid >> 2;
    const int lc = (tid & 3) << 3;
    const unsigned short* Ag = A + (size_t)(m0 + lr) * Kd + k0 + lc;
    const unsigned short* Bg = B + (size_t)(n0 + lr) * Kd + k0 + lc;
    const size_t rowStep = (size_t)64 * Kd;

    unsigned dstA[2], dstB[2];
    dstA[0] = (unsigned)__cvta_generic_to_shared(&As[0][lr*40 + lc]);
    dstA[1] = (unsigned)__cvta_generic_to_shared(&As[1][lr*40 + lc]);
    dstB[0] = (unsigned)__cvta_generic_to_shared(&Bs[0][lr*40 + lc]);
    dstB[1] = (unsigned)__cvta_generic_to_shared(&Bs[1][lr*40 + lc]);

    float acc[4][4][4];
    #pragma unroll
    for (int mi = 0; mi < 4; mi++)
        #pragma unroll
        for (int ni = 0; ni < 4; ni++)
            #pragma unroll
            for (int q = 0; q < 4; q++) acc[mi][ni][q] = 0.f;

    {
        cp16(dstA[0], Ag); cp16(dstA[0] + 5120, Ag + rowStep);
        cp16(dstB[0], Bg); cp16(dstB[0] + 5120, Bg + rowStep);
        CP_COMMIT();
    }

    for (int kk = 0; kk < nIter; kk++) {
        int cur = kk & 1;
        if (kk + 1 < nIter) {
            const unsigned short* ap = Ag + ((kk+1) << 5);
            const unsigned short* bp = Bg + ((kk+1) << 5);
            cp16(dstA[cur^1], ap); cp16(dstA[cur^1] + 5120, ap + rowStep);
            cp16(dstB[cur^1], bp); cp16(dstB[cur^1] + 5120, bp + rowStep);
            CP_COMMIT();
            asm volatile("cp.async.wait_group 1;\n");
        } else {
            asm volatile("cp.async.wait_group 0;\n");
        }
        __syncthreads();

        const unsigned short* as_ = As[cur];
        const unsigned short* bs_ = Bs[cur];
        #pragma unroll
        for (int ks = 0; ks < 2; ks++) {
            unsigned a[4][4], b[4][2];
            #pragma unroll
            for (int mi = 0; mi < 4; mi++) {
                int row = wm*64 + mi*16;
                const unsigned short* p  = &as_[(row + g)*40 + ks*16 + 2*t];
                const unsigned short* p2 = p + 8*40;
                a[mi][0] = *(const unsigned*)p;
                a[mi][1] = *(const unsigned*)p2;
                a[mi][2] = *(const unsigned*)(p + 8);
                a[mi][3] = *(const unsigned*)(p2 + 8);
            }
            #pragma unroll
            for (int ni = 0; ni < 4; ni++) {
                int col = wn*32 + ni*8;
                const unsigned short* p = &bs_[(col + g)*40 + ks*16 + 2*t];
                b[ni][0] = *(const unsigned*)p;
                b[ni][1] = *(const unsigned*)(p + 8);
            }
            #pragma unroll
            for (int mi = 0; mi < 4; mi++)
                #pragma unroll
                for (int ni = 0; ni < 4; ni++)
                    MMA16816(acc[mi][ni][0], acc[mi][ni][1], acc[mi][ni][2], acc[mi][ni][3],
                             a[mi][0], a[mi][1], a[mi][2], a[mi][3], b[ni][0], b[ni][1]);
        }
        __syncthreads();
    }

    const bool direct = (gridDim.z == 1);
    float* Cz = direct ? C : C + (size_t)blockIdx.z * M * N;
    #pragma unroll
    for (int mi = 0; mi < 4; mi++)
        #pragma unroll
        for (int ni = 0; ni < 4; ni++) {
            int row = m0 + wm*64 + mi*16 + g;
            int col = n0 + wn*32 + ni*8 + 2*t;
            float v0 = acc[mi][ni][0], v1 = acc[mi][ni][1];
            float v2 = acc[mi][ni][2], v3 = acc[mi][ni][3];
            if (direct) {
                if (bias) { float b0 = bias[col], b1 = bias[col+1]; v0 += b0; v1 += b1; v2 += b0; v3 += b1; }
                if (relu) { v0 = fmaxf(v0,0.f); v1 = fmaxf(v1,0.f); v2 = fmaxf(v2,0.f); v3 = fmaxf(v3,0.f); }
            }
            *(float2*)&Cz[(size_t)row * N + col]       = make_float2(v0, v1);
            *(float2*)&Cz[(size_t)(row + 8) * N + col] = make_float2(v2, v3);
        }
}

// ---------------- fp32 SIMT GEMM (round-2, known-good) ----------------
template<bool BT>
__global__ __launch_bounds__(256, 2) void gemm_kernel(
    const float* __restrict__ A, const float* __restrict__ B, float* __restrict__ C,
    int M, int N, int Kd, int kChunk)
{
    __shared__ float As[8][128];
    __shared__ float Bs[8][128];
    const int tid = threadIdx.x;
    const int tx = tid & 15, ty = tid >> 4;
    const int bn = blockIdx.x, bm = blockIdx.y, bz = blockIdx.z;
    const int k0 = bz * kChunk;

    const int ar = tid >> 1, aq = (tid & 1) << 2;
    const float* Arow = A + (size_t)(bm*128 + ar)*Kd + aq;
    const float* Brow;
    if (BT) Brow = B + (size_t)(bn*128 + ar)*Kd + aq;
    else    Brow = B + (size_t)(k0 + (tid >> 5))*N + bn*128 + ((tid & 31) << 2);

    float acc[8][8];
    #pragma unroll
    for (int r = 0; r < 8; r++)
        #pragma unroll
        for (int c = 0; c < 8; c++) acc[r][c] = 0.f;

    for (int k = k0; k < k0 + kChunk; k += 8) {
        float4 av = *(const float4*)(Arow + k);
        As[aq+0][ar] = av.x; As[aq+1][ar] = av.y; As[aq+2][ar] = av.z; As[aq+3][ar] = av.w;
        if (BT) {
            float4 bv = *(const float4*)(Brow + k);
            Bs[aq+0][ar] = bv.x; Bs[aq+1][ar] = bv.y; Bs[aq+2][ar] = bv.z; Bs[aq+3][ar] = bv.w;
        } else {
            float4 bv = *(const float4*)Brow;
            *(float4*)&Bs[tid >> 5][(tid & 31) << 2] = bv;
            Brow += 8 * (size_t)N;
        }
        __syncthreads();
        #pragma unroll
        for (int kk = 0; kk < 8; kk++) {
            float a[8], b[8];
            *(float4*)&a[0] = *(const float4*)&As[kk][ty << 2];
            *(float4*)&a[4] = *(const float4*)&As[kk][64 + (ty << 2)];
            *(float4*)&b[0] = *(const float4*)&Bs[kk][tx << 2];
            *(float4*)&b[4] = *(const float4*)&Bs[kk][64 + (tx << 2)];
            #pragma unroll
            for (int r = 0; r < 8; r++)
                #pragma unroll
                for (int c = 0; c < 8; c++) acc[r][c] += a[r] * b[c];
        }
        __syncthreads();
    }

    float* Cout = C + (size_t)bz * M * N;
    const int mbase = bm*128, nbase = bn*128;
    #pragma unroll
    for (int rh = 0; rh < 2; rh++)
        #pragma unroll
        for (int rr = 0; rr < 4; rr++) {
            int r = rh*4 + rr;
            int m = mbase + rh*64 + (ty << 2) + rr;
            float* crow = Cout + (size_t)m * N + nbase;
            *(float4*)(crow + (tx << 2))      = make_float4(acc[r][0], acc[r][1], acc[r][2], acc[r][3]);
            *(float4*)(crow + 64 + (tx << 2)) = make_float4(acc[r][4], acc[r][5], acc[r][6], acc[r][7]);
        }
}

__global__ void reduce_kernel(const float* __restrict__ P, float* __restrict__ C,
                              const float* __restrict__ bias, int MN, int N, int split, int relu)
{
    int idx = blockIdx.x * 256 + threadIdx.x;
    if (idx >= MN) return;
    float s = 0.f;
    for (int z = 0; z < split; z++) s += P[(size_t)z * MN + idx];
    if (bias) s += bias[idx % N];
    if (relu) s = fmaxf(s, 0.f);
    C[idx] = s;
}

__global__ void rowmax_kernel(const float* __restrict__ base, float* __restrict__ m)
{
    int i = blockIdx.x, tid = threadIdx.x;
    const float* row = base + (size_t)i * SLOTSN;
    float mx = -FLT_MAX;
    for (int s = tid; s < SLOTSN; s += 256) mx = fmaxf(mx, row[s]);
    for (int o = 16; o; o >>= 1) mx = fmaxf(mx, __shfl_down_sync(0xffffffffu, mx, o));
    __shared__ float sh[8];
    if ((tid & 31) == 0) sh[tid >> 5] = mx;
    __syncthreads();
    if (tid == 0) { float r = sh[0]; for (int w = 1; w < 8; w++) r = fmaxf(r, sh[w]); m[i] = r; }
}

// E = exp(base - m) fp32 (round-2), Z0 row sums, candidate collection
__global__ void e_kernel(const float* __restrict__ base, const float* __restrict__ m,
                         float* __restrict__ E, float* __restrict__ Z0,
                         float* __restrict__ cval, int* __restrict__ cslot, int* __restrict__ ccnt)
{
    int i = blockIdx.x, tid = threadIdx.x;
    __shared__ int cnt;
    if (tid == 0) cnt = 0;
    __syncthreads();
    float mi = m[i], thr = mi - CDELTA, z = 0.f;
    const float* row = base + (size_t)i * SLOTSN;
    float* erow = E + (size_t)i * SLOTSN;
    for (int s = tid; s < SLOTSN; s += 256) {
        float b = row[s];
        float e = __expf(b - mi);
        erow[s] = e;
        z += e;
        if (b >= thr) {
            int idx = atomicAdd(&cnt, 1);
            if (idx < CCAP) { cval[i*CCAP + idx] = b; cslot[i*CCAP + idx] = s; }
        }
    }
    for (int o = 16; o; o >>= 1) z += __shfl_down_sync(0xffffffffu, z, o);
    __shared__ float sh[8];
    if ((tid & 31) == 0) sh[tid >> 5] = z;
    __syncthreads();
    if (tid == 0) { float r = 0; for (int w = 0; w < 8; w++) r += sh[w]; Z0[i] = r; ccnt[i] = cnt; }
}

__device__ __forceinline__ unsigned long long mk_key(float v, int slot)
{
    unsigned u = __float_as_uint(v);
    u = (u & 0x80000000u) ? ~u : (u | 0x80000000u);
    return ((unsigned long long)u << 32) | (unsigned)(0xFFFFFFFFu - (unsigned)slot);
}

// sequential slot chain — single warp, register-prefetched
__global__ void seq_kernel(const float* __restrict__ G,
                           const float* __restrict__ cval, const int* __restrict__ cslot,
                           const int* __restrict__ ccnt, const float* __restrict__ base,
                           int* __restrict__ slots_out, int* __restrict__ nxt_out)
{
    extern __shared__ short mapw[];
    __shared__ int slots_s[256];
    __shared__ unsigned char alive[256];
    __shared__ short nxt[256];
    int lane = threadIdx.x;

    for (int s = lane * 8; s < SLOTSN; s += 256)
        *(int4*)&mapw[s] = make_int4(-1, -1, -1, -1);
    for (int j = lane; j < 256; j += 32) { alive[j] = 0; nxt[j] = 1000; }
    __syncwarp();

    float4 rg0 = *(const float4*)&G[lane * 8];
    float4 rg1 = *(const float4*)&G[lane * 8 + 4];
    int pcnt = ccnt[0];
    float pv[4]; int ps[4];
    #pragma unroll
    for (int q = 0; q < 4; q++) {
        pv[q] = cval[lane + 32*q];
        ps[q] = cslot[lane + 32*q];
    }

    for (int i = 0; i < 256; i++) {
        float gv[8] = {rg0.x, rg0.y, rg0.z, rg0.w, rg1.x, rg1.y, rg1.z, rg1.w};
        int cnt = pcnt;
        float cv[4]; int cs[4];
        #pragma unroll
        for (int q = 0; q < 4; q++) { cv[q] = pv[q]; cs[q] = ps[q]; }

        if (i + 1 < 256) {
            rg0 = *(const float4*)&G[(i+1)*256 + lane*8];
            rg1 = *(const float4*)&G[(i+1)*256 + lane*8 + 4];
            pcnt = ccnt[i+1];
            #pragma unroll
            for (int q = 0; q < 4; q++) {
                pv[q] = cval[(i+1)*CCAP + lane + 32*q];
                ps[q] = cslot[(i+1)*CCAP + lane + 32*q];
            }
        }

        unsigned long long best = 0ull;
        #pragma unroll
        for (int q = 0; q < 8; q++) {
            int j = lane*8 + q;
            if (j < i && alive[j]) {
                unsigned long long k = mk_key(gv[q], slots_s[j]);
                if (k > best) best = k;
            }
        }
        bool needfull = (cnt > CCAP);
        bool found = false;
        if (!needfull) {
            #pragma unroll
            for (int q = 0; q < 4; q++) {
                int c = lane + 32*q;
                if (c < cnt && mapw[cs[q]] < 0) {
                    found = true;
                    unsigned long long k = mk_key(cv[q], cs[q]);
                    if (k > best) best = k;
                }
            }
            for (int c = lane + 128; c < cnt; c += 32) {
                int s = cslot[i*CCAP + c];
                if (mapw[s] < 0) {
                    found = true;
                    unsigned long long k = mk_key(cval[i*CCAP + c], s);
                    if (k > best) best = k;
                }
            }
        }
        if (!__any_sync(0xffffffffu, found) || needfull) {
            const float* row = base + (size_t)i * SLOTSN;
            for (int s4 = lane*4; s4 < SLOTSN; s4 += 128) {
                float4 v = *(const float4*)&row[s4];
                float vv[4] = {v.x, v.y, v.z, v.w};
                #pragma unroll
                for (int q = 0; q < 4; q++)
                    if (mapw[s4+q] < 0) {
                        unsigned long long k = mk_key(vv[q], s4+q);
                        if (k > best) best = k;
                    }
            }
        }
        #pragma unroll
        for (int o = 16; o; o >>= 1) {
            unsigned long long k = __shfl_xor_sync(0xffffffffu, best, o);
            if (k > best) best = k;
        }
        int slot = (int)(0xFFFFFFFFu - (unsigned)(best & 0xFFFFFFFFull));
        if (lane == 0) {
            int old = mapw[slot];
            if (old >= 0) { alive[old] = 0; nxt[old] = (short)i; }
            mapw[slot] = (short)i;
            alive[i] = 1;
            slots_s[i] = slot;
        }
        __syncwarp();
    }
    for (int j = lane; j < 256; j += 32) { slots_out[j] = slots_s[j]; nxt_out[j] = nxt[j]; }
}

// correction coefficients (round-2: reads fp32 E)
__global__ void cbuild_kernel(const float* __restrict__ G, const float* __restrict__ m,
                              const float* __restrict__ E, const int* __restrict__ slots,
                              const int* __restrict__ nxt, float* __restrict__ Ccat,
                              float* __restrict__ Zc)
{
    int i = blockIdx.x, j = threadIdx.x;
    float c1 = 0.f, c2 = 0.f;
    if (j < i && nxt[j] >= i) {
        c1 = __expf(G[i*256 + j] - m[i]);
        c2 = E[(size_t)i * SLOTSN + slots[j]];
    }
    Ccat[i*512 + j] = c1;
    Ccat[i*512 + 256 + j] = -c2;
    float d = c1 - c2;
    for (int o = 16; o; o >>= 1) d += __shfl_down_sync(0xffffffffu, d, o);
    __shared__ float sh[8];
    if ((j & 31) == 0) sh[j >> 5] = d;
    __syncthreads();
    if (j == 0) { float r = 0; for (int w = 0; w < 8; w++) r += sh[w]; Zc[i] = r; }
}

__global__ void vcat_kernel(const float* __restrict__ V, const float* __restrict__ mv,
                            const int* __restrict__ slots, float* __restrict__ Vcat)
{
    int j = blockIdx.x, d = threadIdx.x;
    if (j < 256) Vcat[(size_t)j*512 + d] = V[j*512 + d];
    else         Vcat[(size_t)j*512 + d] = mv[(size_t)slots[j-256]*512 + d];
}

__global__ void merged_kernel(const float* __restrict__ S, const float* __restrict__ R0,
                              const float* __restrict__ Rc, const float* __restrict__ Z0,
                              const float* __restrict__ Zc, float* __restrict__ Mg)
{
    int i = blockIdx.x, d = threadIdx.x;
    Mg[i*1024 + d] = S[i*512 + d];
    Mg[i*1024 + 512 + d] = (R0[i*512 + d] + Rc[i*512 + d]) / (Z0[i] + Zc[i]);
}

extern "C" void kernel_launch(void* const* d_in, const int* in_sizes, int n_in,
                              void* d_out, int out_size)
{
    (void)in_sizes; (void)n_in; (void)out_size;
    const float* S  = (const float*)d_in[0];
    const float* MK = (const float*)d_in[1];
    const float* MV = (const float*)d_in[2];
    const float* Wk = (const float*)d_in[3];
    const float* bk = (const float*)d_in[4];
    const float* Wv = (const float*)d_in[5];
    const float* bv = (const float*)d_in[6];
    const float* W1 = (const float*)d_in[7];
    const float* b1 = (const float*)d_in[8];
    const float* W2 = (const float*)d_in[9];
    const float* b2 = (const float*)d_in[10];
    float* out = (float*)d_out;

    float *pK, *pV, *pG, *pBase, *pE, *pm, *pZ0, *pZc, *pR0, *pRc;
    float *pCval, *pCcat, *pVcat, *pMg, *pHid, *pPart;
    int *pCslot, *pCcnt, *pSlots, *pNxt;
    unsigned short *pMKp6, *pKpA6;
    cudaGetSymbolAddress((void**)&pK, g_K);
    cudaGetSymbolAddress((void**)&pV, g_V);
    cudaGetSymbolAddress((void**)&pG, g_G);
    cudaGetSymbolAddress((void**)&pBase, g_base);
    cudaGetSymbolAddress((void**)&pE, g_E);
    cudaGetSymbolAddress((void**)&pm, g_m);
    cudaGetSymbolAddress((void**)&pZ0, g_Z0);
    cudaGetSymbolAddress((void**)&pZc, g_Zc);
    cudaGetSymbolAddress((void**)&pR0, g_R0);
    cudaGetSymbolAddress((void**)&pRc, g_Rc);
    cudaGetSymbolAddress((void**)&pCval, g_cand_val);
    cudaGetSymbolAddress((void**)&pCslot, g_cand_slot);
    cudaGetSymbolAddress((void**)&pCcnt, g_cand_cnt);
    cudaGetSymbolAddress((void**)&pSlots, g_slots);
    cudaGetSymbolAddress((void**)&pNxt, g_nxt);
    cudaGetSymbolAddress((void**)&pCcat, g_Ccat);
    cudaGetSymbolAddress((void**)&pVcat, g_Vcat);
    cudaGetSymbolAddress((void**)&pMg, g_Merged);
    cudaGetSymbolAddress((void**)&pHid, g_Hidden);
    cudaGetSymbolAddress((void**)&pPart, g_Part);
    cudaGetSymbolAddress((void**)&pMKp6, g_MKp6);
    cudaGetSymbolAddress((void**)&pKpA6, g_KpA6);

    dim3 thr(256);

    // pack mem_keys for the base GEMM (6-term B-mode)
    pack_split6_kernel<<<(SLOTSN*DDIM + 255)/256, thr>>>(MK, pMKp6, SLOTSN*DDIM, DDIM, 1);

    // projections (fp32 SIMT, exact): K = S@Wk^T, V = S@Wv^T   (biases are zero but kept)
    gemm_kernel<true><<<dim3(4, 2, 8), thr>>>(S, Wk, pPart, 256, 512, 512, 64);
    reduce_kernel<<<512, 256>>>(pPart, pK, bk, 256*512, 512, 8, 0);
    gemm_kernel<true><<<dim3(4, 2, 8), thr>>>(S, Wv, pPart, 256, 512, 512, 64);
    reduce_kernel<<<512, 256>>>(pPart, pV, bv, 256*512, 512, 8, 0);

    pack_split6_kernel<<<(BATCHN*DDIM + 255)/256, thr>>>(pK, pKpA6, BATCHN*DDIM, DDIM, 0);

    // Gram G = K@K^T (fp32 SIMT — exact for argmax)
    gemm_kernel<true><<<dim3(2, 2, 16), thr>>>(pK, pK, pPart, 256, 256, 512, 32);
    reduce_kernel<<<256, 256>>>(pPart, pG, nullptr, 256*256, 256, 16, 0);

    // base = K @ mem_keys^T (tensor cores, 6-term split-bf16 = fp32-class)
    mma_tn_kernel<<<dim3(256, 2, 1), thr>>>(pKpA6, pMKp6, pBase, nullptr, 256, 32768, K6_MK, K6_MK, 0);
    rowmax_kernel<<<256, 256>>>(pBase, pm);
    e_kernel<<<256, 256>>>(pBase, pm, pE, pZ0, pCval, pCslot, pCcnt);

    // R0 = E @ mem_vals (fp32 SIMT, round-2, split-K 32)
    gemm_kernel<false><<<dim3(4, 2, 32), thr>>>(pE, MV, pPart, 256, 512, 32768, 1024);
    reduce_kernel<<<512, 256>>>(pPart, pR0, nullptr, 256*512, 512, 32, 0);

    // sequential slot chain (1 warp)
    cudaFuncSetAttribute(seq_kernel, cudaFuncAttributeMaxDynamicSharedMemorySize, SLOTSN * 2);
    seq_kernel<<<1, 32, SLOTSN * 2>>>(pG, pCval, pCslot, pCcnt, pBase, pSlots, pNxt);

    // per-step corrections: Rc = Ccat @ Vcat (fp32 SIMT)
    cbuild_kernel<<<256, 256>>>(pG, pm, pE, pSlots, pNxt, pCcat, pZc);
    vcat_kernel<<<512, 512>>>(pV, MV, pSlots, pVcat);
    gemm_kernel<false><<<dim3(4, 2, 8), thr>>>(pCcat, pVcat, pPart, 256, 512, 512, 64);
    reduce_kernel<<<512, 256>>>(pPart, pRc, nullptr, 256*512, 512, 8, 0);

    merged_kernel<<<256, 512>>>(S, pR0, pRc, pZ0, pZc, pMg);

    // MLP (fp32 SIMT, round-2)
    gemm_kernel<true><<<dim3(16, 2, 8), thr>>>(pMg, W1, pPart, 256, 2048, 1024, 128);
    reduce_kernel<<<2048, 256>>>(pPart, pHid, b1, 256*2048, 2048, 8, 1);
    gemm_kernel<true><<<dim3(4, 2, 32), thr>>>(pHid, W2, pPart, 256, 512, 2048, 64);
    reduce_kernel<<<512, 256>>>(pPart, out, b2, 256*512, 512, 32, 0);
}

// round 13
// speedup vs baseline: 1.7852x; 1.1577x over previous
#include <cuda_runtime.h>
#include <cuda_bf16.h>
#include <cuda_fp16.h>
#include <cstdint>
#include <float.h>

#define BATCHN 256
#define DDIM   512
#define HDIM   2048
#define SLOTSN 32768
#define CCAP   512
#define CDELTA 12.0f
#define PART_ELEMS (32*256*512)
#define K3_MK   (3*DDIM)      // 1536
#define K3_MLP1 (3*2*DDIM)    // 3072
#define K3_MLP2 (3*HDIM)      // 6144

// ---------------- scratch (static device globals; no allocation) ----------------
__device__ float g_K[BATCHN*DDIM];
__device__ float g_V[BATCHN*DDIM];
__device__ float g_G[BATCHN*BATCHN];
__device__ float g_base[(size_t)BATCHN*SLOTSN];
__device__ float g_E[(size_t)BATCHN*SLOTSN];
__device__ float g_m[BATCHN];
__device__ float g_Z0[BATCHN];
__device__ float g_Zc[BATCHN];
__device__ float g_R0[BATCHN*DDIM];
__device__ float g_Rc[BATCHN*DDIM];
__device__ float g_cand_val[BATCHN*CCAP];
__device__ int   g_cand_slot[BATCHN*CCAP];
__device__ int   g_cand_cnt[BATCHN];
__device__ int   g_slots[BATCHN];
__device__ int   g_nxt[BATCHN];
__device__ float g_Ccat[BATCHN*2*BATCHN];
__device__ float g_Vcat[2*BATCHN*DDIM];
__device__ float g_Merged[BATCHN*2*DDIM];
__device__ float g_Hidden[BATCHN*HDIM];
__device__ float g_Part[PART_ELEMS];

// fp16 2-way-split (3-term) packed operands
__device__ unsigned short g_MKp3[(size_t)SLOTSN*K3_MK];   // 100 MB
__device__ unsigned short g_KpA3[BATCHN*K3_MK];
__device__ unsigned short g_Mgp3[BATCHN*K3_MLP1];
__device__ unsigned short g_W1p3[(size_t)HDIM*K3_MLP1];
__device__ unsigned short g_Hidp3[BATCHN*K3_MLP2];
__device__ unsigned short g_W2p3[(size_t)DDIM*K3_MLP2];

// ---------------- helpers ----------------
__device__ __forceinline__ unsigned short f2h(float x) {
    __half h = __float2half_rn(x);
    return *reinterpret_cast<unsigned short*>(&h);
}
__device__ __forceinline__ float h2f(unsigned short u) {
    __half h = *reinterpret_cast<__half*>(&u);
    return __half2float(h);
}
__device__ __forceinline__ void cp16(unsigned d, const void* s) {
    asm volatile("cp.async.cg.shared.global [%0], [%1], 16;\n" :: "r"(d), "l"(s));
}
#define CP_COMMIT() asm volatile("cp.async.commit_group;\n")
#define MMA16816H(C0,C1,C2,C3,A0,A1,A2,A3,B0,B1) \
  asm volatile("mma.sync.aligned.m16n8k16.row.col.f32.f16.f16.f32 " \
    "{%0,%1,%2,%3},{%4,%5,%6,%7},{%8,%9},{%0,%1,%2,%3};\n" \
    : "+f"(C0),"+f"(C1),"+f"(C2),"+f"(C3) \
    : "r"(A0),"r"(A1),"r"(A2),"r"(A3),"r"(B0),"r"(B1))
__device__ __forceinline__ void ldsm_x4(unsigned &r0, unsigned &r1, unsigned &r2, unsigned &r3, unsigned addr) {
    asm volatile("ldmatrix.sync.aligned.m8n8.x4.shared.b16 {%0,%1,%2,%3}, [%4];"
        : "=r"(r0), "=r"(r1), "=r"(r2), "=r"(r3) : "r"(addr));
}
__device__ __forceinline__ void ldsm_x2(unsigned &r0, unsigned &r1, unsigned addr) {
    asm volatile("ldmatrix.sync.aligned.m8n8.x2.shared.b16 {%0,%1}, [%2];"
        : "=r"(r0), "=r"(r1) : "r"(addr));
}

// ---------------- fp16 3-term packing ----------------
// A-mode: [h1|h1|h2], B-mode: [h1|h2|h1]; product sum = h1b1 + h1b2 + h2b1
// error ~3*2^-22 relative per product: fp32-class.
__global__ void pack_split3h_kernel(const float* __restrict__ X, unsigned short* __restrict__ Y,
                                    int total, int Kd, int bmode)
{
    int idx = blockIdx.x * 256 + threadIdx.x;
    if (idx >= total) return;
    int r = idx / Kd, k = idx - r * Kd;
    float x = X[idx];
    unsigned short h1 = f2h(x);
    unsigned short h2 = f2h(x - h2f(h1));
    size_t ro = (size_t)r * (3 * Kd);
    Y[ro + k] = h1;
    Y[ro + Kd + k] = bmode ? h2 : h1;
    Y[ro + 2*Kd + k] = bmode ? h1 : h2;
}

// ---------------- fp16 TN tensor-core GEMM (ldmatrix inner loop) ----------------
// C[m,n] = sum_k A[m,k]*B[n,k]; A [M,Kd] row, B [N,Kd] row (fp16 bits).
__global__ __launch_bounds__(256, 2) void mma_tn_kernel(
    const unsigned short* __restrict__ A, const unsigned short* __restrict__ B,
    float* __restrict__ C, const float* __restrict__ bias,
    int M, int N, int Kd, int kChunk, int relu)
{
    __shared__ unsigned short As[2][128*40];
    __shared__ unsigned short Bs[2][128*40];
    const int tid = threadIdx.x;
    const int wid = tid >> 5, lane = tid & 31;
    const int wm = wid >> 2, wn = wid & 3;     // 2 x 4 warp grid
    const int g = lane >> 2, t = lane & 3;
    const int m0 = blockIdx.y * 128, n0 = blockIdx.x * 128;
    const int k0 = blockIdx.z * kChunk;
    const int nIter = kChunk >> 5;

    const int lr = tid >> 2;
    const int lc = (tid & 3) << 3;
    const unsigned short* Ag = A + (size_t)(m0 + lr) * Kd + k0 + lc;
    const unsigned short* Bg = B + (size_t)(n0 + lr) * Kd + k0 + lc;
    const size_t rowStep = (size_t)64 * Kd;

    unsigned dstA[2], dstB[2];
    dstA[0] = (unsigned)__cvta_generic_to_shared(&As[0][lr*40 + lc]);
    dstA[1] = (unsigned)__cvta_generic_to_shared(&As[1][lr*40 + lc]);
    dstB[0] = (unsigned)__cvta_generic_to_shared(&Bs[0][lr*40 + lc]);
    dstB[1] = (unsigned)__cvta_generic_to_shared(&Bs[1][lr*40 + lc]);

    // ldmatrix source addresses (fixed per thread, offset by stage/ks/mi/ni)
    unsigned aAddr[2], bAddr[2];
    {
        int arow = wm*64 + (lane & 15);
        int acol = (lane >> 4) << 3;             // 0 or 8
        aAddr[0] = (unsigned)__cvta_generic_to_shared(&As[0][arow*40 + acol]);
        aAddr[1] = (unsigned)__cvta_generic_to_shared(&As[1][arow*40 + acol]);
        int brow = wn*32 + (lane & 7);
        int bcol = ((lane >> 3) & 1) << 3;       // 0 or 8 (lanes 16-31 unused but valid)
        bAddr[0] = (unsigned)__cvta_generic_to_shared(&Bs[0][brow*40 + bcol]);
        bAddr[1] = (unsigned)__cvta_generic_to_shared(&Bs[1][brow*40 + bcol]);
    }

    float acc[4][4][4];
    #pragma unroll
    for (int mi = 0; mi < 4; mi++)
        #pragma unroll
        for (int ni = 0; ni < 4; ni++)
            #pragma unroll
            for (int q = 0; q < 4; q++) acc[mi][ni][q] = 0.f;

    {
        cp16(dstA[0], Ag); cp16(dstA[0] + 5120, Ag + rowStep);
        cp16(dstB[0], Bg); cp16(dstB[0] + 5120, Bg + rowStep);
        CP_COMMIT();
    }

    for (int kk = 0; kk < nIter; kk++) {
        int cur = kk & 1;
        if (kk + 1 < nIter) {
            const unsigned short* ap = Ag + ((kk+1) << 5);
            const unsigned short* bp = Bg + ((kk+1) << 5);
            cp16(dstA[cur^1], ap); cp16(dstA[cur^1] + 5120, ap + rowStep);
            cp16(dstB[cur^1], bp); cp16(dstB[cur^1] + 5120, bp + rowStep);
            CP_COMMIT();
            asm volatile("cp.async.wait_group 1;\n");
        } else {
            asm volatile("cp.async.wait_group 0;\n");
        }
        __syncthreads();

        #pragma unroll
        for (int ks = 0; ks < 2; ks++) {
            unsigned a[4][4], b[4][2];
            #pragma unroll
            for (int mi = 0; mi < 4; mi++)
                ldsm_x4(a[mi][0], a[mi][1], a[mi][2], a[mi][3],
                        aAddr[cur] + (mi*16*40 + ks*16) * 2);
            #pragma unroll
            for (int ni = 0; ni < 4; ni++)
                ldsm_x2(b[ni][0], b[ni][1],
                        bAddr[cur] + (ni*8*40 + ks*16) * 2);
            #pragma unroll
            for (int mi = 0; mi < 4; mi++)
                #pragma unroll
                for (int ni = 0; ni < 4; ni++)
                    MMA16816H(acc[mi][ni][0], acc[mi][ni][1], acc[mi][ni][2], acc[mi][ni][3],
                              a[mi][0], a[mi][1], a[mi][2], a[mi][3], b[ni][0], b[ni][1]);
        }
        __syncthreads();
    }

    const bool direct = (gridDim.z == 1);
    float* Cz = direct ? C : C + (size_t)blockIdx.z * M * N;
    #pragma unroll
    for (int mi = 0; mi < 4; mi++)
        #pragma unroll
        for (int ni = 0; ni < 4; ni++) {
            int row = m0 + wm*64 + mi*16 + g;
            int col = n0 + wn*32 + ni*8 + 2*t;
            float v0 = acc[mi][ni][0], v1 = acc[mi][ni][1];
            float v2 = acc[mi][ni][2], v3 = acc[mi][ni][3];
            if (direct) {
                if (bias) { float b0 = bias[col], b1 = bias[col+1]; v0 += b0; v1 += b1; v2 += b0; v3 += b1; }
                if (relu) { v0 = fmaxf(v0,0.f); v1 = fmaxf(v1,0.f); v2 = fmaxf(v2,0.f); v3 = fmaxf(v3,0.f); }
            }
            *(float2*)&Cz[(size_t)row * N + col]       = make_float2(v0, v1);
            *(float2*)&Cz[(size_t)(row + 8) * N + col] = make_float2(v2, v3);
        }
}

// ---------------- fp32 SIMT GEMM (exact ops: proj, G, R0, Rc) ----------------
template<bool BT>
__global__ __launch_bounds__(256, 2) void gemm_kernel(
    const float* __restrict__ A, const float* __restrict__ B, float* __restrict__ C,
    int M, int N, int Kd, int kChunk)
{
    __shared__ float As[8][128];
    __shared__ float Bs[8][128];
    const int tid = threadIdx.x;
    const int tx = tid & 15, ty = tid >> 4;
    const int bn = blockIdx.x, bm = blockIdx.y, bz = blockIdx.z;
    const int k0 = bz * kChunk;

    const int ar = tid >> 1, aq = (tid & 1) << 2;
    const float* Arow = A + (size_t)(bm*128 + ar)*Kd + aq;
    const float* Brow;
    if (BT) Brow = B + (size_t)(bn*128 + ar)*Kd + aq;
    else    Brow = B + (size_t)(k0 + (tid >> 5))*N + bn*128 + ((tid & 31) << 2);

    float acc[8][8];
    #pragma unroll
    for (int r = 0; r < 8; r++)
        #pragma unroll
        for (int c = 0; c < 8; c++) acc[r][c] = 0.f;

    for (int k = k0; k < k0 + kChunk; k += 8) {
        float4 av = *(const float4*)(Arow + k);
        As[aq+0][ar] = av.x; As[aq+1][ar] = av.y; As[aq+2][ar] = av.z; As[aq+3][ar] = av.w;
        if (BT) {
            float4 bv = *(const float4*)(Brow + k);
            Bs[aq+0][ar] = bv.x; Bs[aq+1][ar] = bv.y; Bs[aq+2][ar] = bv.z; Bs[aq+3][ar] = bv.w;
        } else {
            float4 bv = *(const float4*)Brow;
            *(float4*)&Bs[tid >> 5][(tid & 31) << 2] = bv;
            Brow += 8 * (size_t)N;
        }
        __syncthreads();
        #pragma unroll
        for (int kk = 0; kk < 8; kk++) {
            float a[8], b[8];
            *(float4*)&a[0] = *(const float4*)&As[kk][ty << 2];
            *(float4*)&a[4] = *(const float4*)&As[kk][64 + (ty << 2)];
            *(float4*)&b[0] = *(const float4*)&Bs[kk][tx << 2];
            *(float4*)&b[4] = *(const float4*)&Bs[kk][64 + (tx << 2)];
            #pragma unroll
            for (int r = 0; r < 8; r++)
                #pragma unroll
                for (int c = 0; c < 8; c++) acc[r][c] += a[r] * b[c];
        }
        __syncthreads();
    }

    float* Cout = C + (size_t)bz * M * N;
    const int mbase = bm*128, nbase = bn*128;
    #pragma unroll
    for (int rh = 0; rh < 2; rh++)
        #pragma unroll
        for (int rr = 0; rr < 4; rr++) {
            int r = rh*4 + rr;
            int m = mbase + rh*64 + (ty << 2) + rr;
            float* crow = Cout + (size_t)m * N + nbase;
            *(float4*)(crow + (tx << 2))      = make_float4(acc[r][0], acc[r][1], acc[r][2], acc[r][3]);
            *(float4*)(crow + 64 + (tx << 2)) = make_float4(acc[r][4], acc[r][5], acc[r][6], acc[r][7]);
        }
}

__global__ void reduce_kernel(const float* __restrict__ P, float* __restrict__ C,
                              const float* __restrict__ bias, int MN, int N, int split, int relu)
{
    int idx = blockIdx.x * 256 + threadIdx.x;
    if (idx >= MN) return;
    float s = 0.f;
    for (int z = 0; z < split; z++) s += P[(size_t)z * MN + idx];
    if (bias) s += bias[idx % N];
    if (relu) s = fmaxf(s, 0.f);
    C[idx] = s;
}

__global__ void rowmax_kernel(const float* __restrict__ base, float* __restrict__ m)
{
    int i = blockIdx.x, tid = threadIdx.x;
    const float* row = base + (size_t)i * SLOTSN;
    float mx = -FLT_MAX;
    for (int s = tid; s < SLOTSN; s += 256) mx = fmaxf(mx, row[s]);
    for (int o = 16; o; o >>= 1) mx = fmaxf(mx, __shfl_down_sync(0xffffffffu, mx, o));
    __shared__ float sh[8];
    if ((tid & 31) == 0) sh[tid >> 5] = mx;
    __syncthreads();
    if (tid == 0) { float r = sh[0]; for (int w = 1; w < 8; w++) r = fmaxf(r, sh[w]); m[i] = r; }
}

// E = exp(base - m) fp32, Z0 row sums, candidate collection
__global__ void e_kernel(const float* __restrict__ base, const float* __restrict__ m,
                         float* __restrict__ E, float* __restrict__ Z0,
                         float* __restrict__ cval, int* __restrict__ cslot, int* __restrict__ ccnt)
{
    int i = blockIdx.x, tid = threadIdx.x;
    __shared__ int cnt;
    if (tid == 0) cnt = 0;
    __syncthreads();
    float mi = m[i], thr = mi - CDELTA, z = 0.f;
    const float* row = base + (size_t)i * SLOTSN;
    float* erow = E + (size_t)i * SLOTSN;
    for (int s = tid; s < SLOTSN; s += 256) {
        float b = row[s];
        float e = __expf(b - mi);
        erow[s] = e;
        z += e;
        if (b >= thr) {
            int idx = atomicAdd(&cnt, 1);
            if (idx < CCAP) { cval[i*CCAP + idx] = b; cslot[i*CCAP + idx] = s; }
        }
    }
    for (int o = 16; o; o >>= 1) z += __shfl_down_sync(0xffffffffu, z, o);
    __shared__ float sh[8];
    if ((tid & 31) == 0) sh[tid >> 5] = z;
    __syncthreads();
    if (tid == 0) { float r = 0; for (int w = 0; w < 8; w++) r += sh[w]; Z0[i] = r; ccnt[i] = cnt; }
}

__device__ __forceinline__ unsigned long long mk_key(float v, int slot)
{
    unsigned u = __float_as_uint(v);
    u = (u & 0x80000000u) ? ~u : (u | 0x80000000u);
    return ((unsigned long long)u << 32) | (unsigned)(0xFFFFFFFFu - (unsigned)slot);
}

// sequential slot chain — single warp, register-prefetched
__global__ void seq_kernel(const float* __restrict__ G,
                           const float* __restrict__ cval, const int* __restrict__ cslot,
                           const int* __restrict__ ccnt, const float* __restrict__ base,
                           int* __restrict__ slots_out, int* __restrict__ nxt_out)
{
    extern __shared__ short mapw[];
    __shared__ int slots_s[256];
    __shared__ unsigned char alive[256];
    __shared__ short nxt[256];
    int lane = threadIdx.x;

    for (int s = lane * 8; s < SLOTSN; s += 256)
        *(int4*)&mapw[s] = make_int4(-1, -1, -1, -1);
    for (int j = lane; j < 256; j += 32) { alive[j] = 0; nxt[j] = 1000; }
    __syncwarp();

    float4 rg0 = *(const float4*)&G[lane * 8];
    float4 rg1 = *(const float4*)&G[lane * 8 + 4];
    int pcnt = ccnt[0];
    float pv[4]; int ps[4];
    #pragma unroll
    for (int q = 0; q < 4; q++) {
        pv[q] = cval[lane + 32*q];
        ps[q] = cslot[lane + 32*q];
    }

    for (int i = 0; i < 256; i++) {
        float gv[8] = {rg0.x, rg0.y, rg0.z, rg0.w, rg1.x, rg1.y, rg1.z, rg1.w};
        int cnt = pcnt;
        float cv[4]; int cs[4];
        #pragma unroll
        for (int q = 0; q < 4; q++) { cv[q] = pv[q]; cs[q] = ps[q]; }

        if (i + 1 < 256) {
            rg0 = *(const float4*)&G[(i+1)*256 + lane*8];
            rg1 = *(const float4*)&G[(i+1)*256 + lane*8 + 4];
            pcnt = ccnt[i+1];
            #pragma unroll
            for (int q = 0; q < 4; q++) {
                pv[q] = cval[(i+1)*CCAP + lane + 32*q];
                ps[q] = cslot[(i+1)*CCAP + lane + 32*q];
            }
        }

        unsigned long long best = 0ull;
        #pragma unroll
        for (int q = 0; q < 8; q++) {
            int j = lane*8 + q;
            if (j < i && alive[j]) {
                unsigned long long k = mk_key(gv[q], slots_s[j]);
                if (k > best) best = k;
            }
        }
        bool needfull = (cnt > CCAP);
        bool found = false;
        if (!needfull) {
            #pragma unroll
            for (int q = 0; q < 4; q++) {
                int c = lane + 32*q;
                if (c < cnt && mapw[cs[q]] < 0) {
                    found = true;
                    unsigned long long k = mk_key(cv[q], cs[q]);
                    if (k > best) best = k;
                }
            }
            for (int c = lane + 128; c < cnt; c += 32) {
                int s = cslot[i*CCAP + c];
                if (mapw[s] < 0) {
                    found = true;
                    unsigned long long k = mk_key(cval[i*CCAP + c], s);
                    if (k > best) best = k;
                }
            }
        }
        if (!__any_sync(0xffffffffu, found) || needfull) {
            const float* row = base + (size_t)i * SLOTSN;
            for (int s4 = lane*4; s4 < SLOTSN; s4 += 128) {
                float4 v = *(const float4*)&row[s4];
                float vv[4] = {v.x, v.y, v.z, v.w};
                #pragma unroll
                for (int q = 0; q < 4; q++)
                    if (mapw[s4+q] < 0) {
                        unsigned long long k = mk_key(vv[q], s4+q);
                        if (k > best) best = k;
                    }
            }
        }
        #pragma unroll
        for (int o = 16; o; o >>= 1) {
            unsigned long long k = __shfl_xor_sync(0xffffffffu, best, o);
            if (k > best) best = k;
        }
        int slot = (int)(0xFFFFFFFFu - (unsigned)(best & 0xFFFFFFFFull));
        if (lane == 0) {
            int old = mapw[slot];
            if (old >= 0) { alive[old] = 0; nxt[old] = (short)i; }
            mapw[slot] = (short)i;
            alive[i] = 1;
            slots_s[i] = slot;
        }
        __syncwarp();
    }
    for (int j = lane; j < 256; j += 32) { slots_out[j] = slots_s[j]; nxt_out[j] = nxt[j]; }
}

__global__ void cbuild_kernel(const float* __restrict__ G, const float* __restrict__ m,
                              const float* __restrict__ E, const int* __restrict__ slots,
                              const int* __restrict__ nxt, float* __restrict__ Ccat,
                              float* __restrict__ Zc)
{
    int i = blockIdx.x, j = threadIdx.x;
    float c1 = 0.f, c2 = 0.f;
    if (j < i && nxt[j] >= i) {
        c1 = __expf(G[i*256 + j] - m[i]);
        c2 = E[(size_t)i * SLOTSN + slots[j]];
    }
    Ccat[i*512 + j] = c1;
    Ccat[i*512 + 256 + j] = -c2;
    float d = c1 - c2;
    for (int o = 16; o; o >>= 1) d += __shfl_down_sync(0xffffffffu, d, o);
    __shared__ float sh[8];
    if ((j & 31) == 0) sh[j >> 5] = d;
    __syncthreads();
    if (j == 0) { float r = 0; for (int w = 0; w < 8; w++) r += sh[w]; Zc[i] = r; }
}

__global__ void vcat_kernel(const float* __restrict__ V, const float* __restrict__ mv,
                            const int* __restrict__ slots, float* __restrict__ Vcat)
{
    int j = blockIdx.x, d = threadIdx.x;
    if (j < 256) Vcat[(size_t)j*512 + d] = V[j*512 + d];
    else         Vcat[(size_t)j*512 + d] = mv[(size_t)slots[j-256]*512 + d];
}

__global__ void merged_kernel(const float* __restrict__ S, const float* __restrict__ R0,
                              const float* __restrict__ Rc, const float* __restrict__ Z0,
                              const float* __restrict__ Zc, float* __restrict__ Mg)
{
    int i = blockIdx.x, d = threadIdx.x;
    Mg[i*1024 + d] = S[i*512 + d];
    Mg[i*1024 + 512 + d] = (R0[i*512 + d] + Rc[i*512 + d]) / (Z0[i] + Zc[i]);
}

extern "C" void kernel_launch(void* const* d_in, const int* in_sizes, int n_in,
                              void* d_out, int out_size)
{
    (void)in_sizes; (void)n_in; (void)out_size;
    const float* S  = (const float*)d_in[0];
    const float* MK = (const float*)d_in[1];
    const float* MV = (const float*)d_in[2];
    const float* Wk = (const float*)d_in[3];
    const float* bk = (const float*)d_in[4];
    const float* Wv = (const float*)d_in[5];
    const float* bv = (const float*)d_in[6];
    const float* W1 = (const float*)d_in[7];
    const float* b1 = (const float*)d_in[8];
    const float* W2 = (const float*)d_in[9];
    const float* b2 = (const float*)d_in[10];
    float* out = (float*)d_out;

    float *pK, *pV, *pG, *pBase, *pE, *pm, *pZ0, *pZc, *pR0, *pRc;
    float *pCval, *pCcat, *pVcat, *pMg, *pHid, *pPart;
    int *pCslot, *pCcnt, *pSlots, *pNxt;
    unsigned short *pMKp3, *pKpA3, *pMgp3, *pW1p3, *pHidp3, *pW2p3;
    cudaGetSymbolAddress((void**)&pK, g_K);
    cudaGetSymbolAddress((void**)&pV, g_V);
    cudaGetSymbolAddress((void**)&pG, g_G);
    cudaGetSymbolAddress((void**)&pBase, g_base);
    cudaGetSymbolAddress((void**)&pE, g_E);
    cudaGetSymbolAddress((void**)&pm, g_m);
    cudaGetSymbolAddress((void**)&pZ0, g_Z0);
    cudaGetSymbolAddress((void**)&pZc, g_Zc);
    cudaGetSymbolAddress((void**)&pR0, g_R0);
    cudaGetSymbolAddress((void**)&pRc, g_Rc);
    cudaGetSymbolAddress((void**)&pCval, g_cand_val);
    cudaGetSymbolAddress((void**)&pCslot, g_cand_slot);
    cudaGetSymbolAddress((void**)&pCcnt, g_cand_cnt);
    cudaGetSymbolAddress((void**)&pSlots, g_slots);
    cudaGetSymbolAddress((void**)&pNxt, g_nxt);
    cudaGetSymbolAddress((void**)&pCcat, g_Ccat);
    cudaGetSymbolAddress((void**)&pVcat, g_Vcat);
    cudaGetSymbolAddress((void**)&pMg, g_Merged);
    cudaGetSymbolAddress((void**)&pHid, g_Hidden);
    cudaGetSymbolAddress((void**)&pPart, g_Part);
    cudaGetSymbolAddress((void**)&pMKp3, g_MKp3);
    cudaGetSymbolAddress((void**)&pKpA3, g_KpA3);
    cudaGetSymbolAddress((void**)&pMgp3, g_Mgp3);
    cudaGetSymbolAddress((void**)&pW1p3, g_W1p3);
    cudaGetSymbolAddress((void**)&pHidp3, g_Hidp3);
    cudaGetSymbolAddress((void**)&pW2p3, g_W2p3);

    dim3 thr(256);

    // packing of invariant operands (fp16 3-term)
    pack_split3h_kernel<<<(SLOTSN*DDIM + 255)/256, thr>>>(MK, pMKp3, SLOTSN*DDIM, DDIM, 1);
    pack_split3h_kernel<<<(HDIM*2*DDIM + 255)/256, thr>>>(W1, pW1p3, HDIM*2*DDIM, 2*DDIM, 1);
    pack_split3h_kernel<<<(DDIM*HDIM + 255)/256, thr>>>(W2, pW2p3, DDIM*HDIM, HDIM, 1);

    // projections (fp32 SIMT, exact): K = S@Wk^T, V = S@Wv^T
    gemm_kernel<true><<<dim3(4, 2, 8), thr>>>(S, Wk, pPart, 256, 512, 512, 64);
    reduce_kernel<<<512, 256>>>(pPart, pK, bk, 256*512, 512, 8, 0);
    gemm_kernel<true><<<dim3(4, 2, 8), thr>>>(S, Wv, pPart, 256, 512, 512, 64);
    reduce_kernel<<<512, 256>>>(pPart, pV, bv, 256*512, 512, 8, 0);

    pack_split3h_kernel<<<(BATCHN*DDIM + 255)/256, thr>>>(pK, pKpA3, BATCHN*DDIM, DDIM, 0);

    // Gram G = K@K^T (fp32 SIMT — exact for argmax)
    gemm_kernel<true><<<dim3(2, 2, 16), thr>>>(pK, pK, pPart, 256, 256, 512, 32);
    reduce_kernel<<<256, 256>>>(pPart, pG, nullptr, 256*256, 256, 16, 0);

    // base = K @ mem_keys^T (HMMA fp16 3-term, fp32-class accuracy)
    mma_tn_kernel<<<dim3(256, 2, 1), thr>>>(pKpA3, pMKp3, pBase, nullptr, 256, 32768, K3_MK, K3_MK, 0);
    rowmax_kernel<<<256, 256>>>(pBase, pm);
    e_kernel<<<256, 256>>>(pBase, pm, pE, pZ0, pCval, pCslot, pCcnt);

    // R0 = E @ mem_vals (fp32 SIMT, split-K 32)
    gemm_kernel<false><<<dim3(4, 2, 32), thr>>>(pE, MV, pPart, 256, 512, 32768, 1024);
    reduce_kernel<<<512, 256>>>(pPart, pR0, nullptr, 256*512, 512, 32, 0);

    // sequential slot chain (1 warp)
    cudaFuncSetAttribute(seq_kernel, cudaFuncAttributeMaxDynamicSharedMemorySize, SLOTSN * 2);
    seq_kernel<<<1, 32, SLOTSN * 2>>>(pG, pCval, pCslot, pCcnt, pBase, pSlots, pNxt);

    // per-step corrections: Rc = Ccat @ Vcat (fp32 SIMT)
    cbuild_kernel<<<256, 256>>>(pG, pm, pE, pSlots, pNxt, pCcat, pZc);
    vcat_kernel<<<512, 512>>>(pV, MV, pSlots, pVcat);
    gemm_kernel<false><<<dim3(4, 2, 8), thr>>>(pCcat, pVcat, pPart, 256, 512, 512, 64);
    reduce_kernel<<<512, 256>>>(pPart, pRc, nullptr, 256*512, 512, 8, 0);

    merged_kernel<<<256, 512>>>(S, pR0, pRc, pZ0, pZc, pMg);

    // MLP on HMMA fp16 3-term
    pack_split3h_kernel<<<(BATCHN*2*DDIM + 255)/256, thr>>>(pMg, pMgp3, BATCHN*2*DDIM, 2*DDIM, 0);
    mma_tn_kernel<<<dim3(16, 2, 8), thr>>>(pMgp3, pW1p3, pPart, nullptr, 256, 2048, K3_MLP1, K3_MLP1/8, 0);
    reduce_kernel<<<2048, 256>>>(pPart, pHid, b1, 256*2048, 2048, 8, 1);
    pack_split3h_kernel<<<(BATCHN*HDIM + 255)/256, thr>>>(pHid, pHidp3, BATCHN*HDIM, HDIM, 0);
    mma_tn_kernel<<<dim3(4, 2, 16), thr>>>(pHidp3, pW2p3, pPart, nullptr, 256, 512, K3_MLP2, K3_MLP2/16, 0);
    reduce_kernel<<<512, 256>>>(pPart, out, b2, 256*512, 512, 16, 0);
}

// round 14
// speedup vs baseline: 1.9257x; 1.0787x over previous
#include <cuda_runtime.h>
#include <cuda_bf16.h>
#include <cuda_fp16.h>
#include <cstdint>
#include <float.h>

#define BATCHN 256
#define DDIM   512
#define HDIM   2048
#define SLOTSN 32768
#define CCAP   512
#define CDELTA 12.0f
#define PART_ELEMS (32*256*512)
#define K3_MK   (3*DDIM)      // 1536
#define K3_SL   (3*SLOTSN)    // 98304
#define K3_MLP1 (3*2*DDIM)    // 3072
#define K3_MLP2 (3*HDIM)      // 6144

// ---------------- scratch (static device globals; no allocation) ----------------
__device__ float g_K[BATCHN*DDIM];
__device__ float g_V[BATCHN*DDIM];
__device__ float g_G[BATCHN*BATCHN];
__device__ float g_base[(size_t)BATCHN*SLOTSN];
__device__ float g_m[BATCHN];
__device__ float g_Z0[BATCHN];
__device__ float g_Zc[BATCHN];
__device__ float g_R0[BATCHN*DDIM];
__device__ float g_Rc[BATCHN*DDIM];
__device__ float g_cand_val[BATCHN*CCAP];
__device__ int   g_cand_slot[BATCHN*CCAP];
__device__ int   g_cand_cnt[BATCHN];
__device__ int   g_slots[BATCHN];
__device__ int   g_nxt[BATCHN];
__device__ float g_Ccat[BATCHN*2*BATCHN];
__device__ float g_Vcat[2*BATCHN*DDIM];
__device__ float g_Merged[BATCHN*2*DDIM];
__device__ float g_Hidden[BATCHN*HDIM];
__device__ float g_Part[PART_ELEMS];

// fp16 2-way-split (3-term) packed operands
__device__ unsigned short g_MKp3[(size_t)SLOTSN*K3_MK];   // 100 MB
__device__ unsigned short g_KpA3[BATCHN*K3_MK];
__device__ unsigned short g_MVt3[(size_t)DDIM*K3_SL];     // 100 MB
__device__ unsigned short g_Ep3[(size_t)BATCHN*K3_SL];    // 50 MB
__device__ unsigned short g_Mgp3[BATCHN*K3_MLP1];
__device__ unsigned short g_W1p3[(size_t)HDIM*K3_MLP1];
__device__ unsigned short g_Hidp3[BATCHN*K3_MLP2];
__device__ unsigned short g_W2p3[(size_t)DDIM*K3_MLP2];

// ---------------- helpers ----------------
__device__ __forceinline__ unsigned short f2h(float x) {
    __half h = __float2half_rn(x);
    return *reinterpret_cast<unsigned short*>(&h);
}
__device__ __forceinline__ float h2f(unsigned short u) {
    __half h = *reinterpret_cast<__half*>(&u);
    return __half2float(h);
}
__device__ __forceinline__ void cp16(unsigned d, const void* s) {
    asm volatile("cp.async.cg.shared.global [%0], [%1], 16;\n" :: "r"(d), "l"(s));
}
#define CP_COMMIT() asm volatile("cp.async.commit_group;\n")
#define MMA16816H(C0,C1,C2,C3,A0,A1,A2,A3,B0,B1) \
  asm volatile("mma.sync.aligned.m16n8k16.row.col.f32.f16.f16.f32 " \
    "{%0,%1,%2,%3},{%4,%5,%6,%7},{%8,%9},{%0,%1,%2,%3};\n" \
    : "+f"(C0),"+f"(C1),"+f"(C2),"+f"(C3) \
    : "r"(A0),"r"(A1),"r"(A2),"r"(A3),"r"(B0),"r"(B1))
__device__ __forceinline__ void ldsm_x4(unsigned &r0, unsigned &r1, unsigned &r2, unsigned &r3, unsigned addr) {
    asm volatile("ldmatrix.sync.aligned.m8n8.x4.shared.b16 {%0,%1,%2,%3}, [%4];"
        : "=r"(r0), "=r"(r1), "=r"(r2), "=r"(r3) : "r"(addr));
}
__device__ __forceinline__ void ldsm_x2(unsigned &r0, unsigned &r1, unsigned addr) {
    asm volatile("ldmatrix.sync.aligned.m8n8.x2.shared.b16 {%0,%1}, [%2];"
        : "=r"(r0), "=r"(r1) : "r"(addr));
}

// ---------------- fp16 3-term packing ----------------
// A-mode: [h1|h1|h2], B-mode: [h1|h2|h1]; product sum = h1b1 + h1b2 + h2b1
__global__ void pack_split3h_kernel(const float* __restrict__ X, unsigned short* __restrict__ Y,
                                    int total, int Kd, int bmode)
{
    int idx = blockIdx.x * 256 + threadIdx.x;
    if (idx >= total) return;
    int r = idx / Kd, k = idx - r * Kd;
    float x = X[idx];
    unsigned short h1 = f2h(x);
    unsigned short h2 = f2h(x - h2f(h1));
    size_t ro = (size_t)r * (3 * Kd);
    Y[ro + k] = h1;
    Y[ro + Kd + k] = bmode ? h2 : h1;
    Y[ro + 2*Kd + k] = bmode ? h1 : h2;
}

// MV [SLOTSN, DDIM] -> MVt3 [DDIM, 3*SLOTSN] fp16 B-mode [h1|h2|h1]
__global__ void transpose_pack3h_kernel(const float* __restrict__ X, unsigned short* __restrict__ Y)
{
    __shared__ float tile[32][33];
    int r0 = blockIdx.x * 32, c0 = blockIdx.y * 32;
    int tx = threadIdx.x, ty = threadIdx.y;     // (32, 8)
    #pragma unroll
    for (int q = 0; q < 4; q++)
        tile[ty + 8*q][tx] = X[(size_t)(r0 + ty + 8*q) * DDIM + c0 + tx];
    __syncthreads();
    #pragma unroll
    for (int q = 0; q < 4; q++) {
        int c = c0 + ty + 8*q;
        int r = r0 + tx;
        float x = tile[tx][ty + 8*q];
        unsigned short h1 = f2h(x);
        unsigned short h2 = f2h(x - h2f(h1));
        size_t ro = (size_t)c * K3_SL;
        Y[ro + r] = h1;
        Y[ro + (size_t)SLOTSN + r] = h2;
        Y[ro + 2*(size_t)SLOTSN + r] = h1;
    }
}

// ---------------- fp16 TN tensor-core GEMM (ldmatrix inner loop) ----------------
__global__ __launch_bounds__(256, 2) void mma_tn_kernel(
    const unsigned short* __restrict__ A, const unsigned short* __restrict__ B,
    float* __restrict__ C, const float* __restrict__ bias,
    int M, int N, int Kd, int kChunk, int relu)
{
    __shared__ unsigned short As[2][128*40];
    __shared__ unsigned short Bs[2][128*40];
    const int tid = threadIdx.x;
    const int wid = tid >> 5, lane = tid & 31;
    const int wm = wid >> 2, wn = wid & 3;
    const int g = lane >> 2, t = lane & 3;
    const int m0 = blockIdx.y * 128, n0 = blockIdx.x * 128;
    const int k0 = blockIdx.z * kChunk;
    const int nIter = kChunk >> 5;

    const int lr = tid >> 2;
    const int lc = (tid & 3) << 3;
    const unsigned short* Ag = A + (size_t)(m0 + lr) * Kd + k0 + lc;
    const unsigned short* Bg = B + (size_t)(n0 + lr) * Kd + k0 + lc;
    const size_t rowStep = (size_t)64 * Kd;

    unsigned dstA[2], dstB[2];
    dstA[0] = (unsigned)__cvta_generic_to_shared(&As[0][lr*40 + lc]);
    dstA[1] = (unsigned)__cvta_generic_to_shared(&As[1][lr*40 + lc]);
    dstB[0] = (unsigned)__cvta_generic_to_shared(&Bs[0][lr*40 + lc]);
    dstB[1] = (unsigned)__cvta_generic_to_shared(&Bs[1][lr*40 + lc]);

    unsigned aAddr[2], bAddr[2];
    {
        int arow = wm*64 + (lane & 15);
        int acol = (lane >> 4) << 3;
        aAddr[0] = (unsigned)__cvta_generic_to_shared(&As[0][arow*40 + acol]);
        aAddr[1] = (unsigned)__cvta_generic_to_shared(&As[1][arow*40 + acol]);
        int brow = wn*32 + (lane & 7);
        int bcol = ((lane >> 3) & 1) << 3;
        bAddr[0] = (unsigned)__cvta_generic_to_shared(&Bs[0][brow*40 + bcol]);
        bAddr[1] = (unsigned)__cvta_generic_to_shared(&Bs[1][brow*40 + bcol]);
    }

    float acc[4][4][4];
    #pragma unroll
    for (int mi = 0; mi < 4; mi++)
        #pragma unroll
        for (int ni = 0; ni < 4; ni++)
            #pragma unroll
            for (int q = 0; q < 4; q++) acc[mi][ni][q] = 0.f;

    {
        cp16(dstA[0], Ag); cp16(dstA[0] + 5120, Ag + rowStep);
        cp16(dstB[0], Bg); cp16(dstB[0] + 5120, Bg + rowStep);
        CP_COMMIT();
    }

    for (int kk = 0; kk < nIter; kk++) {
        int cur = kk & 1;
        if (kk + 1 < nIter) {
            const unsigned short* ap = Ag + ((kk+1) << 5);
            const unsigned short* bp = Bg + ((kk+1) << 5);
            cp16(dstA[cur^1], ap); cp16(dstA[cur^1] + 5120, ap + rowStep);
            cp16(dstB[cur^1], bp); cp16(dstB[cur^1] + 5120, bp + rowStep);
            CP_COMMIT();
            asm volatile("cp.async.wait_group 1;\n");
        } else {
            asm volatile("cp.async.wait_group 0;\n");
        }
        __syncthreads();

        #pragma unroll
        for (int ks = 0; ks < 2; ks++) {
            unsigned a[4][4], b[4][2];
            #pragma unroll
            for (int mi = 0; mi < 4; mi++)
                ldsm_x4(a[mi][0], a[mi][1], a[mi][2], a[mi][3],
                        aAddr[cur] + (mi*16*40 + ks*16) * 2);
            #pragma unroll
            for (int ni = 0; ni < 4; ni++)
                ldsm_x2(b[ni][0], b[ni][1],
                        bAddr[cur] + (ni*8*40 + ks*16) * 2);
            #pragma unroll
            for (int mi = 0; mi < 4; mi++)
                #pragma unroll
                for (int ni = 0; ni < 4; ni++)
                    MMA16816H(acc[mi][ni][0], acc[mi][ni][1], acc[mi][ni][2], acc[mi][ni][3],
                              a[mi][0], a[mi][1], a[mi][2], a[mi][3], b[ni][0], b[ni][1]);
        }
        __syncthreads();
    }

    const bool direct = (gridDim.z == 1);
    float* Cz = direct ? C : C + (size_t)blockIdx.z * M * N;
    #pragma unroll
    for (int mi = 0; mi < 4; mi++)
        #pragma unroll
        for (int ni = 0; ni < 4; ni++) {
            int row = m0 + wm*64 + mi*16 + g;
            int col = n0 + wn*32 + ni*8 + 2*t;
            float v0 = acc[mi][ni][0], v1 = acc[mi][ni][1];
            float v2 = acc[mi][ni][2], v3 = acc[mi][ni][3];
            if (direct) {
                if (bias) { float b0 = bias[col], b1 = bias[col+1]; v0 += b0; v1 += b1; v2 += b0; v3 += b1; }
                if (relu) { v0 = fmaxf(v0,0.f); v1 = fmaxf(v1,0.f); v2 = fmaxf(v2,0.f); v3 = fmaxf(v3,0.f); }
            }
            *(float2*)&Cz[(size_t)row * N + col]       = make_float2(v0, v1);
            *(float2*)&Cz[(size_t)(row + 8) * N + col] = make_float2(v2, v3);
        }
}

// ---------------- fp32 SIMT GEMM (exact ops: proj, G, Rc) ----------------
template<bool BT>
__global__ __launch_bounds__(256, 2) void gemm_kernel(
    const float* __restrict__ A, const float* __restrict__ B, float* __restrict__ C,
    int M, int N, int Kd, int kChunk)
{
    __shared__ float As[8][128];
    __shared__ float Bs[8][128];
    const int tid = threadIdx.x;
    const int tx = tid & 15, ty = tid >> 4;
    const int bn = blockIdx.x, bm = blockIdx.y, bz = blockIdx.z;
    const int k0 = bz * kChunk;

    const int ar = tid >> 1, aq = (tid & 1) << 2;
    const float* Arow = A + (size_t)(bm*128 + ar)*Kd + aq;
    const float* Brow;
    if (BT) Brow = B + (size_t)(bn*128 + ar)*Kd + aq;
    else    Brow = B + (size_t)(k0 + (tid >> 5))*N + bn*128 + ((tid & 31) << 2);

    float acc[8][8];
    #pragma unroll
    for (int r = 0; r < 8; r++)
        #pragma unroll
        for (int c = 0; c < 8; c++) acc[r][c] = 0.f;

    for (int k = k0; k < k0 + kChunk; k += 8) {
        float4 av = *(const float4*)(Arow + k);
        As[aq+0][ar] = av.x; As[aq+1][ar] = av.y; As[aq+2][ar] = av.z; As[aq+3][ar] = av.w;
        if (BT) {
            float4 bv = *(const float4*)(Brow + k);
            Bs[aq+0][ar] = bv.x; Bs[aq+1][ar] = bv.y; Bs[aq+2][ar] = bv.z; Bs[aq+3][ar] = bv.w;
        } else {
            float4 bv = *(const float4*)Brow;
            *(float4*)&Bs[tid >> 5][(tid & 31) << 2] = bv;
            Brow += 8 * (size_t)N;
        }
        __syncthreads();
        #pragma unroll
        for (int kk = 0; kk < 8; kk++) {
            float a[8], b[8];
            *(float4*)&a[0] = *(const float4*)&As[kk][ty << 2];
            *(float4*)&a[4] = *(const float4*)&As[kk][64 + (ty << 2)];
            *(float4*)&b[0] = *(const float4*)&Bs[kk][tx << 2];
            *(float4*)&b[4] = *(const float4*)&Bs[kk][64 + (tx << 2)];
            #pragma unroll
            for (int r = 0; r < 8; r++)
                #pragma unroll
                for (int c = 0; c < 8; c++) acc[r][c] += a[r] * b[c];
        }
        __syncthreads();
    }

    float* Cout = C + (size_t)bz * M * N;
    const int mbase = bm*128, nbase = bn*128;
    #pragma unroll
    for (int rh = 0; rh < 2; rh++)
        #pragma unroll
        for (int rr = 0; rr < 4; rr++) {
            int r = rh*4 + rr;
            int m = mbase + rh*64 + (ty << 2) + rr;
            float* crow = Cout + (size_t)m * N + nbase;
            *(float4*)(crow + (tx << 2))      = make_float4(acc[r][0], acc[r][1], acc[r][2], acc[r][3]);
            *(float4*)(crow + 64 + (tx << 2)) = make_float4(acc[r][4], acc[r][5], acc[r][6], acc[r][7]);
        }
}

__global__ void reduce_kernel(const float* __restrict__ P, float* __restrict__ C,
                              const float* __restrict__ bias, int MN, int N, int split, int relu)
{
    int idx = blockIdx.x * 256 + threadIdx.x;
    if (idx >= MN) return;
    float s = 0.f;
    for (int z = 0; z < split; z++) s += P[(size_t)z * MN + idx];
    if (bias) s += bias[idx % N];
    if (relu) s = fmaxf(s, 0.f);
    C[idx] = s;
}

__global__ void rowmax_kernel(const float* __restrict__ base, float* __restrict__ m)
{
    int i = blockIdx.x, tid = threadIdx.x;
    const float* row = base + (size_t)i * SLOTSN;
    float mx = -FLT_MAX;
    for (int s = tid; s < SLOTSN; s += 256) mx = fmaxf(mx, row[s]);
    for (int o = 16; o; o >>= 1) mx = fmaxf(mx, __shfl_down_sync(0xffffffffu, mx, o));
    __shared__ float sh[8];
    if ((tid & 31) == 0) sh[tid >> 5] = mx;
    __syncthreads();
    if (tid == 0) { float r = sh[0]; for (int w = 1; w < 8; w++) r = fmaxf(r, sh[w]); m[i] = r; }
}

// Ep3 = fp16 3-term A-mode pack of exp(base - m); Z0 row sums; candidates
__global__ void e_kernel(const float* __restrict__ base, const float* __restrict__ m,
                         unsigned short* __restrict__ Ep, float* __restrict__ Z0,
                         float* __restrict__ cval, int* __restrict__ cslot, int* __restrict__ ccnt)
{
    int i = blockIdx.x, tid = threadIdx.x;
    __shared__ int cnt;
    if (tid == 0) cnt = 0;
    __syncthreads();
    float mi = m[i], thr = mi - CDELTA, z = 0.f;
    const float* row = base + (size_t)i * SLOTSN;
    size_t ro = (size_t)i * K3_SL;
    for (int s = tid; s < SLOTSN; s += 256) {
        float b = row[s];
        float e = __expf(b - mi);
        unsigned short h1 = f2h(e);
        unsigned short h2 = f2h(e - h2f(h1));
        Ep[ro + s] = h1;
        Ep[ro + (size_t)SLOTSN + s] = h1;
        Ep[ro + 2*(size_t)SLOTSN + s] = h2;
        z += e;
        if (b >= thr) {
            int idx = atomicAdd(&cnt, 1);
            if (idx < CCAP) { cval[i*CCAP + idx] = b; cslot[i*CCAP + idx] = s; }
        }
    }
    for (int o = 16; o; o >>= 1) z += __shfl_down_sync(0xffffffffu, z, o);
    __shared__ float sh[8];
    if ((tid & 31) == 0) sh[tid >> 5] = z;
    __syncthreads();
    if (tid == 0) { float r = 0; for (int w = 0; w < 8; w++) r += sh[w]; Z0[i] = r; ccnt[i] = cnt; }
}

__device__ __forceinline__ unsigned long long mk_key(float v, int slot)
{
    unsigned u = __float_as_uint(v);
    u = (u & 0x80000000u) ? ~u : (u | 0x80000000u);
    return ((unsigned long long)u << 32) | (unsigned)(0xFFFFFFFFu - (unsigned)slot);
}

// sequential slot chain — single warp, register-prefetched
__global__ void seq_kernel(const float* __restrict__ G,
                           const float* __restrict__ cval, const int* __restrict__ cslot,
                           const int* __restrict__ ccnt, const float* __restrict__ base,
                           int* __restrict__ slots_out, int* __restrict__ nxt_out)
{
    extern __shared__ short mapw[];
    __shared__ int slots_s[256];
    __shared__ unsigned char alive[256];
    __shared__ short nxt[256];
    int lane = threadIdx.x;

    for (int s = lane * 8; s < SLOTSN; s += 256)
        *(int4*)&mapw[s] = make_int4(-1, -1, -1, -1);
    for (int j = lane; j < 256; j += 32) { alive[j] = 0; nxt[j] = 1000; }
    __syncwarp();

    float4 rg0 = *(const float4*)&G[lane * 8];
    float4 rg1 = *(const float4*)&G[lane * 8 + 4];
    int pcnt = ccnt[0];
    float pv[4]; int ps[4];
    #pragma unroll
    for (int q = 0; q < 4; q++) {
        pv[q] = cval[lane + 32*q];
        ps[q] = cslot[lane + 32*q];
    }

    for (int i = 0; i < 256; i++) {
        float gv[8] = {rg0.x, rg0.y, rg0.z, rg0.w, rg1.x, rg1.y, rg1.z, rg1.w};
        int cnt = pcnt;
        float cv[4]; int cs[4];
        #pragma unroll
        for (int q = 0; q < 4; q++) { cv[q] = pv[q]; cs[q] = ps[q]; }

        if (i + 1 < 256) {
            rg0 = *(const float4*)&G[(i+1)*256 + lane*8];
            rg1 = *(const float4*)&G[(i+1)*256 + lane*8 + 4];
            pcnt = ccnt[i+1];
            #pragma unroll
            for (int q = 0; q < 4; q++) {
                pv[q] = cval[(i+1)*CCAP + lane + 32*q];
                ps[q] = cslot[(i+1)*CCAP + lane + 32*q];
            }
        }

        unsigned long long best = 0ull;
        #pragma unroll
        for (int q = 0; q < 8; q++) {
            int j = lane*8 + q;
            if (j < i && alive[j]) {
                unsigned long long k = mk_key(gv[q], slots_s[j]);
                if (k > best) best = k;
            }
        }
        bool needfull = (cnt > CCAP);
        bool found = false;
        if (!needfull) {
            #pragma unroll
            for (int q = 0; q < 4; q++) {
                int c = lane + 32*q;
                if (c < cnt && mapw[cs[q]] < 0) {
                    found = true;
                    unsigned long long k = mk_key(cv[q], cs[q]);
                    if (k > best) best = k;
                }
            }
            for (int c = lane + 128; c < cnt; c += 32) {
                int s = cslot[i*CCAP + c];
                if (mapw[s] < 0) {
                    found = true;
                    unsigned long long k = mk_key(cval[i*CCAP + c], s);
                    if (k > best) best = k;
                }
            }
        }
        if (!__any_sync(0xffffffffu, found) || needfull) {
            const float* row = base + (size_t)i * SLOTSN;
            for (int s4 = lane*4; s4 < SLOTSN; s4 += 128) {
                float4 v = *(const float4*)&row[s4];
                float vv[4] = {v.x, v.y, v.z, v.w};
                #pragma unroll
                for (int q = 0; q < 4; q++)
                    if (mapw[s4+q] < 0) {
                        unsigned long long k = mk_key(vv[q], s4+q);
                        if (k > best) best = k;
                    }
            }
        }
        #pragma unroll
        for (int o = 16; o; o >>= 1) {
            unsigned long long k = __shfl_xor_sync(0xffffffffu, best, o);
            if (k > best) best = k;
        }
        int slot = (int)(0xFFFFFFFFu - (unsigned)(best & 0xFFFFFFFFull));
        if (lane == 0) {
            int old = mapw[slot];
            if (old >= 0) { alive[old] = 0; nxt[old] = (short)i; }
            mapw[slot] = (short)i;
            alive[i] = 1;
            slots_s[i] = slot;
        }
        __syncwarp();
    }
    for (int j = lane; j < 256; j += 32) { slots_out[j] = slots_s[j]; nxt_out[j] = nxt[j]; }
}

// corrections: recompute exp from base (bit-identical to e_kernel's fp32 value)
__global__ void cbuild_kernel(const float* __restrict__ G, const float* __restrict__ m,
                              const float* __restrict__ base, const int* __restrict__ slots,
                              const int* __restrict__ nxt, float* __restrict__ Ccat,
                              float* __restrict__ Zc)
{
    int i = blockIdx.x, j = threadIdx.x;
    float c1 = 0.f, c2 = 0.f;
    if (j < i && nxt[j] >= i) {
        c1 = __expf(G[i*256 + j] - m[i]);
        c2 = __expf(base[(size_t)i * SLOTSN + slots[j]] - m[i]);
    }
    Ccat[i*512 + j] = c1;
    Ccat[i*512 + 256 + j] = -c2;
    float d = c1 - c2;
    for (int o = 16; o; o >>= 1) d += __shfl_down_sync(0xffffffffu, d, o);
    __shared__ float sh[8];
    if ((j & 31) == 0) sh[j >> 5] = d;
    __syncthreads();
    if (j == 0) { float r = 0; for (int w = 0; w < 8; w++) r += sh[w]; Zc[i] = r; }
}

__global__ void vcat_kernel(const float* __restrict__ V, const float* __restrict__ mv,
                            const int* __restrict__ slots, float* __restrict__ Vcat)
{
    int j = blockIdx.x, d = threadIdx.x;
    if (j < 256) Vcat[(size_t)j*512 + d] = V[j*512 + d];
    else         Vcat[(size_t)j*512 + d] = mv[(size_t)slots[j-256]*512 + d];
}

__global__ void merged_kernel(const float* __restrict__ S, const float* __restrict__ R0,
                              const float* __restrict__ Rc, const float* __restrict__ Z0,
                              const float* __restrict__ Zc, float* __restrict__ Mg)
{
    int i = blockIdx.x, d = threadIdx.x;
    Mg[i*1024 + d] = S[i*512 + d];
    Mg[i*1024 + 512 + d] = (R0[i*512 + d] + Rc[i*512 + d]) / (Z0[i] + Zc[i]);
}

extern "C" void kernel_launch(void* const* d_in, const int* in_sizes, int n_in,
                              void* d_out, int out_size)
{
    (void)in_sizes; (void)n_in; (void)out_size;
    const float* S  = (const float*)d_in[0];
    const float* MK = (const float*)d_in[1];
    const float* MV = (const float*)d_in[2];
    const float* Wk = (const float*)d_in[3];
    const float* bk = (const float*)d_in[4];
    const float* Wv = (const float*)d_in[5];
    const float* bv = (const float*)d_in[6];
    const float* W1 = (const float*)d_in[7];
    const float* b1 = (const float*)d_in[8];
    const float* W2 = (const float*)d_in[9];
    const float* b2 = (const float*)d_in[10];
    float* out = (float*)d_out;

    float *pK, *pV, *pG, *pBase, *pm, *pZ0, *pZc, *pR0, *pRc;
    float *pCval, *pCcat, *pVcat, *pMg, *pHid, *pPart;
    int *pCslot, *pCcnt, *pSlots, *pNxt;
    unsigned short *pMKp3, *pKpA3, *pMVt3, *pEp3, *pMgp3, *pW1p3, *pHidp3, *pW2p3;
    cudaGetSymbolAddress((void**)&pK, g_K);
    cudaGetSymbolAddress((void**)&pV, g_V);
    cudaGetSymbolAddress((void**)&pG, g_G);
    cudaGetSymbolAddress((void**)&pBase, g_base);
    cudaGetSymbolAddress((void**)&pm, g_m);
    cudaGetSymbolAddress((void**)&pZ0, g_Z0);
    cudaGetSymbolAddress((void**)&pZc, g_Zc);
    cudaGetSymbolAddress((void**)&pR0, g_R0);
    cudaGetSymbolAddress((void**)&pRc, g_Rc);
    cudaGetSymbolAddress((void**)&pCval, g_cand_val);
    cudaGetSymbolAddress((void**)&pCslot, g_cand_slot);
    cudaGetSymbolAddress((void**)&pCcnt, g_cand_cnt);
    cudaGetSymbolAddress((void**)&pSlots, g_slots);
    cudaGetSymbolAddress((void**)&pNxt, g_nxt);
    cudaGetSymbolAddress((void**)&pCcat, g_Ccat);
    cudaGetSymbolAddress((void**)&pVcat, g_Vcat);
    cudaGetSymbolAddress((void**)&pMg, g_Merged);
    cudaGetSymbolAddress((void**)&pHid, g_Hidden);
    cudaGetSymbolAddress((void**)&pPart, g_Part);
    cudaGetSymbolAddress((void**)&pMKp3, g_MKp3);
    cudaGetSymbolAddress((void**)&pKpA3, g_KpA3);
    cudaGetSymbolAddress((void**)&pMVt3, g_MVt3);
    cudaGetSymbolAddress((void**)&pEp3, g_Ep3);
    cudaGetSymbolAddress((void**)&pMgp3, g_Mgp3);
    cudaGetSymbolAddress((void**)&pW1p3, g_W1p3);
    cudaGetSymbolAddress((void**)&pHidp3, g_Hidp3);
    cudaGetSymbolAddress((void**)&pW2p3, g_W2p3);

    dim3 thr(256);

    // packing of invariant operands (fp16 3-term)
    pack_split3h_kernel<<<(SLOTSN*DDIM + 255)/256, thr>>>(MK, pMKp3, SLOTSN*DDIM, DDIM, 1);
    transpose_pack3h_kernel<<<dim3(SLOTSN/32, DDIM/32), dim3(32, 8)>>>(MV, pMVt3);
    pack_split3h_kernel<<<(HDIM*2*DDIM + 255)/256, thr>>>(W1, pW1p3, HDIM*2*DDIM, 2*DDIM, 1);
    pack_split3h_kernel<<<(DDIM*HDIM + 255)/256, thr>>>(W2, pW2p3, DDIM*HDIM, HDIM, 1);

    // projections (fp32 SIMT, exact): K = S@Wk^T, V = S@Wv^T
    gemm_kernel<true><<<dim3(4, 2, 8), thr>>>(S, Wk, pPart, 256, 512, 512, 64);
    reduce_kernel<<<512, 256>>>(pPart, pK, bk, 256*512, 512, 8, 0);
    gemm_kernel<true><<<dim3(4, 2, 8), thr>>>(S, Wv, pPart, 256, 512, 512, 64);
    reduce_kernel<<<512, 256>>>(pPart, pV, bv, 256*512, 512, 8, 0);

    pack_split3h_kernel<<<(BATCHN*DDIM + 255)/256, thr>>>(pK, pKpA3, BATCHN*DDIM, DDIM, 0);

    // Gram G = K@K^T (fp32 SIMT — exact for argmax)
    gemm_kernel<true><<<dim3(2, 2, 16), thr>>>(pK, pK, pPart, 256, 256, 512, 32);
    reduce_kernel<<<256, 256>>>(pPart, pG, nullptr, 256*256, 256, 16, 0);

    // base = K @ mem_keys^T (HMMA fp16 3-term)
    mma_tn_kernel<<<dim3(256, 2, 1), thr>>>(pKpA3, pMKp3, pBase, nullptr, 256, 32768, K3_MK, K3_MK, 0);
    rowmax_kernel<<<256, 256>>>(pBase, pm);
    e_kernel<<<256, 256>>>(pBase, pm, pEp3, pZ0, pCval, pCslot, pCcnt);

    // R0 = E @ mem_vals (HMMA fp16 3-term, split-K 16)
    mma_tn_kernel<<<dim3(4, 2, 16), thr>>>(pEp3, pMVt3, pPart, nullptr, 256, 512, K3_SL, K3_SL/16, 0);
    reduce_kernel<<<512, 256>>>(pPart, pR0, nullptr, 256*512, 512, 16, 0);

    // sequential slot chain (1 warp)
    cudaFuncSetAttribute(seq_kernel, cudaFuncAttributeMaxDynamicSharedMemorySize, SLOTSN * 2);
    seq_kernel<<<1, 32, SLOTSN * 2>>>(pG, pCval, pCslot, pCcnt, pBase, pSlots, pNxt);

    // per-step corrections: Rc = Ccat @ Vcat (fp32 SIMT)
    cbuild_kernel<<<256, 256>>>(pG, pm, pBase, pSlots, pNxt, pCcat, pZc);
    vcat_kernel<<<512, 512>>>(pV, MV, pSlots, pVcat);
    gemm_kernel<false><<<dim3(4, 2, 8), thr>>>(pCcat, pVcat, pPart, 256, 512, 512, 64);
    reduce_kernel<<<512, 256>>>(pPart, pRc, nullptr, 256*512, 512, 8, 0);

    merged_kernel<<<256, 512>>>(S, pR0, pRc, pZ0, pZc, pMg);

    // MLP on HMMA fp16 3-term
    pack_split3h_kernel<<<(BATCHN*2*DDIM + 255)/256, thr>>>(pMg, pMgp3, BATCHN*2*DDIM, 2*DDIM, 0);
    mma_tn_kernel<<<dim3(16, 2, 8), thr>>>(pMgp3, pW1p3, pPart, nullptr, 256, 2048, K3_MLP1, K3_MLP1/8, 0);
    reduce_kernel<<<2048, 256>>>(pPart, pHid, b1, 256*2048, 2048, 8, 1);
    pack_split3h_kernel<<<(BATCHN*HDIM + 255)/256, thr>>>(pHid, pHidp3, BATCHN*HDIM, HDIM, 0);
    mma_tn_kernel<<<dim3(4, 2, 16), thr>>>(pHidp3, pW2p3, pPart, nullptr, 256, 512, K3_MLP2, K3_MLP2/16, 0);
    reduce_kernel<<<512, 256>>>(pPart, out, b2, 256*512, 512, 16, 0);
}